// round 8
// baseline (speedup 1.0000x reference)
#include <cuda_runtime.h>
#include <math.h>
#include <stdint.h>

// Problem constants
#define B_  32
#define S_  1024
#define D_  256
#define N_  32
#define C_  64

// pass kernel tiling
#define SCH 32                // s-values per block
#define CHUNKS (S_/SCH)       // 32
#define TPB 512               // threads per pass block
#define XPAD 260              // xS row stride (floats)
#define PPAD 272              // pS row stride (272 % 32 == 16 -> conflict-free phase2)
#define CPAD 36               // agree/coef row stride
#define WPAD 65               // W smem row stride (capsule)

#define PASS_SMEM  ((SCH*XPAD + N_*PPAD + SCH*CPAD) * 4)          // 72704 B -> 3 CTAs/SM
#define CAPS_SMEM  ((D_*WPAD + 8*D_ + 8*C_ + 8*C_) * 4)           // 78848 B

// ---------------- scratch (device globals; no runtime allocation) ----------
__device__ float g_y0[B_*D_];          // (1/N) * sum_s x
__device__ float g_ya[B_*N_*D_];       // y for iter1
__device__ float g_yb[B_*N_*D_];       // y for iter2
__device__ float g_v [B_*N_*C_];
__device__ float g_p [B_*N_*D_];       // p[b,n,d] = sum_c W[n,d,c] v[b,n,c]
__device__ float g_logits[B_*S_*N_];

// packed f32x2 helpers
__device__ __forceinline__ void fma2(unsigned long long& d,
                                     unsigned long long a, unsigned long long b) {
    asm("fma.rn.f32x2 %0, %1, %2, %0;" : "+l"(d) : "l"(a), "l"(b));
}
__device__ __forceinline__ unsigned long long pack2(float lo, float hi) {
    unsigned long long v;
    asm("mov.b64 %0, {%1, %2};" : "=l"(v) : "f"(lo), "f"(hi));
    return v;
}
__device__ __forceinline__ float2 unpack2(unsigned long long v) {
    float2 f;
    asm("mov.b64 {%0, %1}, %2;" : "=f"(f.x), "=f"(f.y) : "l"(v));
    return f;
}

// ---------------- zero ------------------------------------------------------
__global__ void zero_kernel() {
    int i = blockIdx.x * blockDim.x + threadIdx.x;
    if (i < B_*D_) g_y0[i] = 0.f;
    if (i < B_*N_*D_) { g_ya[i] = 0.f; g_yb[i] = 0.f; }
}

// ---------------- y0 = (1/N) * sum_s x --------------------------------------
__global__ __launch_bounds__(256) void reduce_x_kernel(const float* __restrict__ x) {
    const int b  = blockIdx.x >> 3;     // 32
    const int sg = blockIdx.x & 7;      // 8 groups x 128 s
    const int d  = threadIdx.x;
    const float* xp = x + ((size_t)b * S_ + sg * 128) * D_ + d;
    float a0 = 0.f, a1 = 0.f, a2 = 0.f, a3 = 0.f;
    #pragma unroll 8
    for (int s = 0; s < 128; s += 4) {
        a0 += xp[(s+0)*D_]; a1 += xp[(s+1)*D_];
        a2 += xp[(s+2)*D_]; a3 += xp[(s+3)*D_];
    }
    atomicAdd(&g_y0[b*D_ + d], (a0+a1+a2+a3) * (1.0f / (float)N_));
}

// ---------------- capsule: s = y@W, v = squash(s), p = W@v -------------------
// grid (N_, B_/8), 256 threads. ysel: 0->g_y0 (n-uniform), 1->g_ya, 2->g_yb.
__global__ __launch_bounds__(256) void capsule_kernel(const float* __restrict__ W,
                                                      int ysel, float* __restrict__ vout_ext,
                                                      int compute_p) {
    extern __shared__ float sm[];
    float* sW = sm;                 // [D_][WPAD]
    float* sy = sW + D_*WPAD;       // [8][D_]
    float* ss = sy + 8*D_;          // [8][C_]
    float* sv = ss + 8*C_;          // [8][C_]

    const int n  = blockIdx.x;
    const int b0 = blockIdx.y * 8;
    const int t  = threadIdx.x;

    const float* Wn = W + (size_t)n * D_ * C_;
    for (int i = t; i < D_*C_; i += 256) {
        int d = i >> 6, c = i & 63;
        sW[d*WPAD + c] = Wn[i];
    }
    const float* ysrc = (ysel == 0) ? g_y0 : (ysel == 1) ? g_ya : g_yb;
    for (int i = t; i < 8*D_; i += 256) {
        int bb = i >> 8, d = i & 255;
        sy[bb*D_ + d] = (ysel == 0) ? ysrc[(b0+bb)*D_ + d]
                                    : ysrc[((size_t)(b0+bb)*N_ + n)*D_ + d];
    }
    __syncthreads();

    // s[b][c] = sum_d y[b][d] * W[d][c]
    {
        const int c = t & 63, bt = t >> 6;
        float s0 = 0.f, s1 = 0.f;
        const float* y0r = sy + (bt*2+0)*D_;
        const float* y1r = sy + (bt*2+1)*D_;
        #pragma unroll 4
        for (int d = 0; d < D_; d++) {
            float w = sW[d*WPAD + c];
            s0 += y0r[d] * w;
            s1 += y1r[d] * w;
        }
        ss[(bt*2+0)*C_ + c] = s0;
        ss[(bt*2+1)*C_ + c] = s1;
    }
    __syncthreads();

    // squash: warp wid handles b = b0+wid
    const int wid = t >> 5, lane = t & 31;
    {
        float a0 = ss[wid*C_ + lane];
        float a1 = ss[wid*C_ + 32 + lane];
        float sq = a0*a0 + a1*a1;
        #pragma unroll
        for (int o = 16; o > 0; o >>= 1) sq += __shfl_xor_sync(0xffffffffu, sq, o);
        float sc = (sq / (1.f + sq)) * rsqrtf(sq + 1e-8f);
        float v0 = a0 * sc, v1 = a1 * sc;
        sv[wid*C_ + lane]      = v0;
        sv[wid*C_ + 32 + lane] = v1;
        float* vo = (vout_ext ? vout_ext : g_v) + ((size_t)(b0+wid)*N_ + n)*C_;
        vo[lane]      = v0;
        vo[32 + lane] = v1;
    }
    __syncthreads();

    // p[b][d] = sum_c W[d][c] * v[b][c]
    if (compute_p) {
        const int b = t >> 5, dl = t & 31;
        const float* vb = sv + b*C_;
        #pragma unroll
        for (int dd = 0; dd < 8; dd++) {
            int d = dd*32 + dl;
            const float* wr = sW + d*WPAD;
            float acc = 0.f;
            #pragma unroll
            for (int cc = 0; cc < C_; cc++) acc += wr[cc] * vb[cc];
            g_p[((size_t)(b0+b)*N_ + n)*D_ + d] = acc;
        }
    }
}

// ---------------- fused routing pass ----------------------------------------
// grid = B_*CHUNKS (1024), 512 threads, 3 CTAs/SM.
// Same memory pattern as round 7; inner FMA loops converted to f32x2.
__global__ __launch_bounds__(TPB, 3) void pass_kernel(const float* __restrict__ x, int first) {
    extern __shared__ float sm[];
    float* xS = sm;                    // [SCH][XPAD]
    float* pS = xS + SCH*XPAD;         // [N_][PPAD]
    float* cS = pS + N_*PPAD;          // [SCH][CPAD]  (agree, then coefficients)

    const int t  = threadIdx.x;
    const int b  = blockIdx.x >> 5;    // CHUNKS = 32
    const int ch = blockIdx.x & 31;
    const int s0 = ch * SCH;

    // load x chunk: SCH rows x 64 float4, coalesced
    {
        const float4* xg = (const float4*)(x + ((size_t)b * S_ + s0) * D_);
        #pragma unroll
        for (int i = t; i < SCH*(D_/4); i += TPB) {
            int s = i >> 6, dq = i & 63;
            *(float4*)&xS[s*XPAD + dq*4] = xg[i];
        }
    }
    // load p[b]: N_ rows x 64 float4
    {
        const float4* pg = (const float4*)(g_p + (size_t)b * N_ * D_);
        #pragma unroll
        for (int i = t; i < N_*(D_/4); i += TPB) {
            int n = i >> 6, dq = i & 63;
            *(float4*)&pS[n*PPAD + dq*4] = pg[i];
        }
    }
    __syncthreads();

    // phase 2: agree[s][n] = sum_d x[s][d] p[n][d]  (packed f32x2 accumulators)
    // warp sg = t>>5 owns rows {2sg, 2sg+1}; ng = (t>>2)&7 owns n-cols {ng+8j};
    // dqq = t&3 splits the 64 float4-dq's 4 ways (interleaved); quad shfl-reduce.
    {
        const int sg  = t >> 5;
        const int ng  = (t >> 2) & 7;
        const int dqq = t & 3;
        unsigned long long ag[2][4];
        #pragma unroll
        for (int i = 0; i < 2; i++)
            #pragma unroll
            for (int j = 0; j < 4; j++) ag[i][j] = 0ull;
        #pragma unroll 4
        for (int k = 0; k < 16; k++) {
            const int dq = dqq + 4*k;
            ulonglong2 x0 = *(const ulonglong2*)&xS[(2*sg+0)*XPAD + dq*4];
            ulonglong2 x1 = *(const ulonglong2*)&xS[(2*sg+1)*XPAD + dq*4];
            #pragma unroll
            for (int j = 0; j < 4; j++) {
                ulonglong2 pv = *(const ulonglong2*)&pS[(ng + 8*j)*PPAD + dq*4];
                fma2(ag[0][j], x0.x, pv.x); fma2(ag[0][j], x0.y, pv.y);
                fma2(ag[1][j], x1.x, pv.x); fma2(ag[1][j], x1.y, pv.y);
            }
        }
        float agf[2][4];
        #pragma unroll
        for (int i = 0; i < 2; i++)
            #pragma unroll
            for (int j = 0; j < 4; j++) {
                float2 f = unpack2(ag[i][j]);
                float v = f.x + f.y;
                v += __shfl_xor_sync(0xffffffffu, v, 1);
                v += __shfl_xor_sync(0xffffffffu, v, 2);
                agf[i][j] = v;
            }
        if (dqq == 0) {
            #pragma unroll
            for (int i = 0; i < 2; i++)
                #pragma unroll
                for (int j = 0; j < 4; j++)
                    cS[(2*sg+i)*CPAD + ng + 8*j] = agf[i][j];
        }
    }
    __syncthreads();

    // softmax over n per s-row; 16 warps x 2 rows
    {
        const int wid = t >> 5, lane = t & 31;
        #pragma unroll
        for (int r = 0; r < SCH/16; r++) {
            int s = wid * (SCH/16) + r;
            float lg = cS[s*CPAD + lane];
            size_t li = ((size_t)b * S_ + s0 + s) * N_ + lane;
            if (first) g_logits[li] = lg;
            else       lg += g_logits[li];
            float mx = lg;
            #pragma unroll
            for (int o = 16; o > 0; o >>= 1) mx = fmaxf(mx, __shfl_xor_sync(0xffffffffu, mx, o));
            float e = expf(lg - mx);
            float sum = e;
            #pragma unroll
            for (int o = 16; o > 0; o >>= 1) sum += __shfl_xor_sync(0xffffffffu, sum, o);
            cS[s*CPAD + lane] = e / sum;
        }
    }
    __syncthreads();

    // phase 3: y[n][d] += sum_s c[s][n] * x[s][d]; thread tile 4n x 4d (packed d-pairs).
    // d = 4*(t&63): lanes consecutive -> conflict-free; c float4 warp-broadcast.
    {
        const int n0 = 4 * (t >> 6);    // 0,4,...,28
        const int dg = t & 63;          // d0 = 4*dg
        unsigned long long acc[4][2];
        #pragma unroll
        for (int i = 0; i < 4; i++) { acc[i][0] = 0ull; acc[i][1] = 0ull; }
        #pragma unroll 4
        for (int s = 0; s < SCH; s++) {
            ulonglong2 xv = *(const ulonglong2*)&xS[s*XPAD + 4*dg];
            float4 cv = *(const float4*)&cS[s*CPAD + n0];
            unsigned long long c0 = pack2(cv.x, cv.x);
            unsigned long long c1 = pack2(cv.y, cv.y);
            unsigned long long c2 = pack2(cv.z, cv.z);
            unsigned long long c3 = pack2(cv.w, cv.w);
            fma2(acc[0][0], c0, xv.x); fma2(acc[0][1], c0, xv.y);
            fma2(acc[1][0], c1, xv.x); fma2(acc[1][1], c1, xv.y);
            fma2(acc[2][0], c2, xv.x); fma2(acc[2][1], c2, xv.y);
            fma2(acc[3][0], c3, xv.x); fma2(acc[3][1], c3, xv.y);
        }
        float* yo = (first ? g_ya : g_yb) + (size_t)b * N_ * D_;
        #pragma unroll
        for (int i = 0; i < 4; i++) {
            float2 a = unpack2(acc[i][0]);
            float2 c = unpack2(acc[i][1]);
            float* row = yo + (n0 + i)*D_ + 4*dg;
            atomicAdd(row + 0, a.x);
            atomicAdd(row + 1, a.y);
            atomicAdd(row + 2, c.x);
            atomicAdd(row + 3, c.y);
        }
    }
}

// ---------------- launch ----------------------------------------------------
extern "C" void kernel_launch(void* const* d_in, const int* in_sizes, int n_in,
                              void* d_out, int out_size) {
    (void)in_sizes; (void)n_in; (void)out_size;
    const float* x = (const float*)d_in[0];
    const float* W = (const float*)d_in[1];
    float* out = (float*)d_out;

    cudaFuncSetAttribute(capsule_kernel, cudaFuncAttributeMaxDynamicSharedMemorySize, CAPS_SMEM);
    cudaFuncSetAttribute(pass_kernel,    cudaFuncAttributeMaxDynamicSharedMemorySize, PASS_SMEM);

    zero_kernel<<<(B_*N_*D_ + 255) / 256, 256>>>();
    reduce_x_kernel<<<B_*8, 256>>>(x);                                  // y0

    capsule_kernel<<<dim3(N_, B_/8), 256, CAPS_SMEM>>>(W, 0, nullptr, 1); // v0, p0
    pass_kernel<<<B_*CHUNKS, TPB, PASS_SMEM>>>(x, 1);                     // iter1 -> g_ya, logits
    capsule_kernel<<<dim3(N_, B_/8), 256, CAPS_SMEM>>>(W, 1, nullptr, 1); // v1, p1
    pass_kernel<<<B_*CHUNKS, TPB, PASS_SMEM>>>(x, 0);                     // iter2 -> g_yb
    capsule_kernel<<<dim3(N_, B_/8), 256, CAPS_SMEM>>>(W, 2, out, 0);     // v2 -> d_out
}

// round 9
// speedup vs baseline: 1.2835x; 1.2835x over previous
#include <cuda_runtime.h>
#include <cuda_bf16.h>
#include <math.h>
#include <stdint.h>

// Problem constants
#define B_  32
#define S_  1024
#define D_  256
#define N_  32
#define C_  64
#define M_  (B_*S_)

// pass kernel tiling (tensor-core version)
#define SCH 32                // s-values per block
#define CHUNKS (S_/SCH)       // 32
#define TPB 256               // 8 warps
#define XPB 528               // x smem row pitch BYTES (264 bf16; 33 x 16B, odd)
#define PPB 528               // p smem row pitch bytes
#define CTPB 80               // cT row pitch bytes (40 bf16; 5 x 16B, odd)
#define CPAD 36               // agree fp32 row stride (floats)

// smem byte offsets
#define O_XH  0
#define O_XL  (O_XH + SCH*XPB)       // 16896
#define O_PH  (O_XL + SCH*XPB)       // 33792
#define O_PL  (O_PH + N_*PPB)        // 50688
#define O_CTH (O_PL + N_*PPB)        // 67584
#define O_CTL (O_CTH + N_*CTPB)      // 70144
#define O_CS  (O_CTL + N_*CTPB)      // 72704
#define PASS_SMEM (O_CS + SCH*CPAD*4)// 77312 B -> 2 CTAs/SM

#define WPAD 65               // W smem row stride (capsule)
#define CAPS_SMEM  ((D_*WPAD + 8*D_ + 8*C_ + 8*C_) * 4)   // 78848 B

// ---------------- scratch (device globals; no runtime allocation) ----------
__device__ float          g_y0[B_*D_];        // (1/N) * sum_s x
__device__ float          g_ya[B_*N_*D_];     // y for iter1
__device__ float          g_yb[B_*N_*D_];     // y for iter2
__device__ float          g_v [B_*N_*C_];
__device__ float          g_logits[B_*S_*N_];
__device__ __nv_bfloat16  g_xhi[(size_t)M_*D_];
__device__ __nv_bfloat16  g_xlo[(size_t)M_*D_];
__device__ __nv_bfloat16  g_phi[B_*N_*D_];
__device__ __nv_bfloat16  g_plo[B_*N_*D_];

// ---------------- PTX helpers ----------------------------------------------
__device__ __forceinline__ uint32_t smem_u32(const void* p) {
    uint32_t a;
    asm("{ .reg .u64 t; cvta.to.shared.u64 t, %1; cvt.u32.u64 %0, t; }" : "=r"(a) : "l"(p));
    return a;
}
#define LDM_X4(r0,r1,r2,r3,a) \
    asm volatile("ldmatrix.sync.aligned.m8n8.x4.shared.b16 {%0,%1,%2,%3}, [%4];" \
        : "=r"(r0),"=r"(r1),"=r"(r2),"=r"(r3) : "r"(a))
#define LDM_X2(r0,r1,a) \
    asm volatile("ldmatrix.sync.aligned.m8n8.x2.shared.b16 {%0,%1}, [%2];" \
        : "=r"(r0),"=r"(r1) : "r"(a))
#define LDM_X4T(r0,r1,r2,r3,a) \
    asm volatile("ldmatrix.sync.aligned.m8n8.x4.trans.shared.b16 {%0,%1,%2,%3}, [%4];" \
        : "=r"(r0),"=r"(r1),"=r"(r2),"=r"(r3) : "r"(a))
__device__ __forceinline__ void mma_bf16(float* c, uint32_t a0, uint32_t a1, uint32_t a2,
                                         uint32_t a3, uint32_t b0, uint32_t b1) {
    asm volatile(
        "mma.sync.aligned.m16n8k16.row.col.f32.bf16.bf16.f32 "
        "{%0,%1,%2,%3}, {%4,%5,%6,%7}, {%8,%9}, {%0,%1,%2,%3};"
        : "+f"(c[0]), "+f"(c[1]), "+f"(c[2]), "+f"(c[3])
        : "r"(a0), "r"(a1), "r"(a2), "r"(a3), "r"(b0), "r"(b1));
}

// ---------------- zero ------------------------------------------------------
__global__ void zero_kernel() {
    int i = blockIdx.x * blockDim.x + threadIdx.x;
    if (i < B_*D_) g_y0[i] = 0.f;
    if (i < B_*N_*D_) { g_ya[i] = 0.f; g_yb[i] = 0.f; }
}

// ---------------- y0 = (1/N) sum_s x ; also emit split-bf16 x ---------------
__global__ __launch_bounds__(256) void reduce_x_kernel(const float* __restrict__ x) {
    const int b  = blockIdx.x >> 3;     // 32
    const int sg = blockIdx.x & 7;      // 8 groups x 128 s
    const int d  = threadIdx.x;
    const size_t base = ((size_t)b * S_ + sg * 128) * D_ + d;
    const float* xp = x + base;
    float a = 0.f;
    #pragma unroll 4
    for (int s = 0; s < 128; s++) {
        float v = xp[(size_t)s * D_];
        __nv_bfloat16 h = __float2bfloat16(v);
        size_t o = base + (size_t)s * D_;
        g_xhi[o] = h;
        g_xlo[o] = __float2bfloat16(v - __bfloat162float(h));
        a += v;
    }
    atomicAdd(&g_y0[b*D_ + d], a * (1.0f / (float)N_));
}

// ---------------- capsule: s = y@W, v = squash(s), p = W@v (split-bf16) -----
__global__ __launch_bounds__(256) void capsule_kernel(const float* __restrict__ W,
                                                      int ysel, float* __restrict__ vout_ext,
                                                      int compute_p) {
    extern __shared__ float sm[];
    float* sW = sm;                 // [D_][WPAD]
    float* sy = sW + D_*WPAD;       // [8][D_]
    float* ss = sy + 8*D_;          // [8][C_]
    float* sv = ss + 8*C_;          // [8][C_]

    const int n  = blockIdx.x;
    const int b0 = blockIdx.y * 8;
    const int t  = threadIdx.x;

    const float* Wn = W + (size_t)n * D_ * C_;
    for (int i = t; i < D_*C_; i += 256) {
        int d = i >> 6, c = i & 63;
        sW[d*WPAD + c] = Wn[i];
    }
    const float* ysrc = (ysel == 0) ? g_y0 : (ysel == 1) ? g_ya : g_yb;
    for (int i = t; i < 8*D_; i += 256) {
        int bb = i >> 8, d = i & 255;
        sy[bb*D_ + d] = (ysel == 0) ? ysrc[(b0+bb)*D_ + d]
                                    : ysrc[((size_t)(b0+bb)*N_ + n)*D_ + d];
    }
    __syncthreads();

    {
        const int c = t & 63, bt = t >> 6;
        float s0 = 0.f, s1 = 0.f;
        const float* y0r = sy + (bt*2+0)*D_;
        const float* y1r = sy + (bt*2+1)*D_;
        #pragma unroll 4
        for (int d = 0; d < D_; d++) {
            float w = sW[d*WPAD + c];
            s0 += y0r[d] * w;
            s1 += y1r[d] * w;
        }
        ss[(bt*2+0)*C_ + c] = s0;
        ss[(bt*2+1)*C_ + c] = s1;
    }
    __syncthreads();

    const int wid = t >> 5, lane = t & 31;
    {
        float a0 = ss[wid*C_ + lane];
        float a1 = ss[wid*C_ + 32 + lane];
        float sq = a0*a0 + a1*a1;
        #pragma unroll
        for (int o = 16; o > 0; o >>= 1) sq += __shfl_xor_sync(0xffffffffu, sq, o);
        float sc = (sq / (1.f + sq)) * rsqrtf(sq + 1e-8f);
        float v0 = a0 * sc, v1 = a1 * sc;
        sv[wid*C_ + lane]      = v0;
        sv[wid*C_ + 32 + lane] = v1;
        float* vo = (vout_ext ? vout_ext : g_v) + ((size_t)(b0+wid)*N_ + n)*C_;
        vo[lane]      = v0;
        vo[32 + lane] = v1;
    }
    __syncthreads();

    if (compute_p) {
        const int b = t >> 5, dl = t & 31;
        const float* vb = sv + b*C_;
        #pragma unroll
        for (int dd = 0; dd < 8; dd++) {
            int d = dd*32 + dl;
            const float* wr = sW + d*WPAD;
            float acc = 0.f;
            #pragma unroll
            for (int cc = 0; cc < C_; cc++) acc += wr[cc] * vb[cc];
            size_t o = ((size_t)(b0+b)*N_ + n)*D_ + d;
            __nv_bfloat16 h = __float2bfloat16(acc);
            g_phi[o] = h;
            g_plo[o] = __float2bfloat16(acc - __bfloat162float(h));
        }
    }
}

// ---------------- fused routing pass (tensor cores) --------------------------
// grid = B_*CHUNKS (1024), 256 threads, 2 CTAs/SM.
__global__ __launch_bounds__(TPB, 2) void pass_kernel(int first) {
    extern __shared__ char smc[];
    char* xh  = smc + O_XH;
    char* xl  = smc + O_XL;
    char* ph  = smc + O_PH;
    char* pl  = smc + O_PL;
    char* cth = smc + O_CTH;
    char* ctl = smc + O_CTL;
    float* cS = (float*)(smc + O_CS);

    const int t = threadIdx.x, wid = t >> 5, lane = t & 31;
    const int b  = blockIdx.x >> 5;
    const int ch = blockIdx.x & 31;
    const int s0 = ch * SCH;

    // load x planes (32 rows x 512B) and p planes (32 rows x 512B), coalesced
    {
        const uint4* sh = (const uint4*)(g_xhi + ((size_t)(b*S_ + s0)) * D_);
        const uint4* sl = (const uint4*)(g_xlo + ((size_t)(b*S_ + s0)) * D_);
        #pragma unroll
        for (int i = t; i < SCH*32; i += TPB) {
            int s = i >> 5, q = i & 31;
            *(uint4*)(xh + s*XPB + q*16) = sh[i];
            *(uint4*)(xl + s*XPB + q*16) = sl[i];
        }
        const uint4* qh = (const uint4*)(g_phi + (size_t)b * N_ * D_);
        const uint4* ql = (const uint4*)(g_plo + (size_t)b * N_ * D_);
        #pragma unroll
        for (int i = t; i < N_*32; i += TPB) {
            int n = i >> 5, q = i & 31;
            *(uint4*)(ph + n*PPB + q*16) = qh[i];
            *(uint4*)(pl + n*PPB + q*16) = ql[i];
        }
    }
    __syncthreads();

    // phase 2: agree = X (32s x 256k) @ P^T -> warp tile m16(s) x n8(n), full K
    {
        const int pm = wid & 1, pn = wid >> 1;       // 2 x 4 warp grid
        const int s0w = pm * 16, n0w = pn * 8;
        const uint32_t aH = smem_u32(xh) + (s0w + (lane & 15))*XPB + (lane >> 4)*16;
        const uint32_t aL = smem_u32(xl) + (s0w + (lane & 15))*XPB + (lane >> 4)*16;
        const uint32_t bH = smem_u32(ph) + (n0w + (lane & 7))*PPB + ((lane >> 3) & 1)*16;
        const uint32_t bL = smem_u32(pl) + (n0w + (lane & 7))*PPB + ((lane >> 3) & 1)*16;
        float c[4] = {0.f, 0.f, 0.f, 0.f};
        #pragma unroll
        for (int k = 0; k < 16; k++) {
            uint32_t ah0,ah1,ah2,ah3, al0,al1,al2,al3, bh0,bh1, bl0,bl1;
            LDM_X4(ah0,ah1,ah2,ah3, aH + k*32);
            LDM_X4(al0,al1,al2,al3, aL + k*32);
            LDM_X2(bh0,bh1, bH + k*32);
            LDM_X2(bl0,bl1, bL + k*32);
            mma_bf16(c, ah0,ah1,ah2,ah3, bh0,bh1);   // hi*hi
            mma_bf16(c, ah0,ah1,ah2,ah3, bl0,bl1);   // hi*lo
            mma_bf16(c, al0,al1,al2,al3, bh0,bh1);   // lo*hi
        }
        const int sr = s0w + (lane >> 2), nc = n0w + (lane & 3)*2;
        cS[sr*CPAD + nc]         = c[0];
        cS[sr*CPAD + nc + 1]     = c[1];
        cS[(sr+8)*CPAD + nc]     = c[2];
        cS[(sr+8)*CPAD + nc + 1] = c[3];
    }
    __syncthreads();

    // softmax over n per s-row; write split-bf16 transposed coefs cT[n][s]
    {
        #pragma unroll
        for (int r = 0; r < 4; r++) {
            int s = wid*4 + r;
            float lg = cS[s*CPAD + lane];
            size_t li = ((size_t)b * S_ + s0 + s) * N_ + lane;
            if (first) g_logits[li] = lg;
            else       lg += g_logits[li];
            float mx = lg;
            #pragma unroll
            for (int o = 16; o > 0; o >>= 1) mx = fmaxf(mx, __shfl_xor_sync(0xffffffffu, mx, o));
            float e = expf(lg - mx);
            float sum = e;
            #pragma unroll
            for (int o = 16; o > 0; o >>= 1) sum += __shfl_xor_sync(0xffffffffu, sum, o);
            float cv = e / sum;
            __nv_bfloat16 hh = __float2bfloat16(cv);
            *(__nv_bfloat16*)(cth + lane*CTPB + s*2) = hh;
            *(__nv_bfloat16*)(ctl + lane*CTPB + s*2) =
                __float2bfloat16(cv - __bfloat162float(hh));
        }
    }
    __syncthreads();

    // phase 3: y = C^T (32n x 32k(s)) @ X (32s x 256d) -> warp m16(n) x 64d
    {
        const int wm = wid & 1, wd = wid >> 1;       // 2 x 4 warp grid
        const int n0w = wm * 16, d0w = wd * 64;
        const uint32_t aH = smem_u32(cth) + (n0w + (lane & 15))*CTPB + (lane >> 4)*16;
        const uint32_t aL = smem_u32(ctl) + (n0w + (lane & 15))*CTPB + (lane >> 4)*16;
        const int part  = lane >> 3;
        const int brow  = (part & 1)*8 + (lane & 7);  // s-row within 16
        const int bcolb = (part >> 1)*16;             // byte offset for d+8 half
        float acc[8][4];
        #pragma unroll
        for (int i = 0; i < 8; i++)
            #pragma unroll
            for (int j = 0; j < 4; j++) acc[i][j] = 0.f;

        #pragma unroll
        for (int ks = 0; ks < 2; ks++) {
            uint32_t ah0,ah1,ah2,ah3, al0,al1,al2,al3;
            LDM_X4(ah0,ah1,ah2,ah3, aH + ks*32);
            LDM_X4(al0,al1,al2,al3, aL + ks*32);
            #pragma unroll
            for (int j = 0; j < 4; j++) {
                const int dd = d0w + j*16;
                const uint32_t xb  = smem_u32(xh) + (ks*16 + brow)*XPB + dd*2 + bcolb;
                const uint32_t xlb = smem_u32(xl) + (ks*16 + brow)*XPB + dd*2 + bcolb;
                uint32_t bh0,bh1,bh2,bh3, bl0,bl1,bl2,bl3;
                LDM_X4T(bh0,bh1,bh2,bh3, xb);
                LDM_X4T(bl0,bl1,bl2,bl3, xlb);
                mma_bf16(acc[2*j],   ah0,ah1,ah2,ah3, bh0,bh1);
                mma_bf16(acc[2*j],   ah0,ah1,ah2,ah3, bl0,bl1);
                mma_bf16(acc[2*j],   al0,al1,al2,al3, bh0,bh1);
                mma_bf16(acc[2*j+1], ah0,ah1,ah2,ah3, bh2,bh3);
                mma_bf16(acc[2*j+1], ah0,ah1,ah2,ah3, bl2,bl3);
                mma_bf16(acc[2*j+1], al0,al1,al2,al3, bh2,bh3);
            }
        }
        float* yo = (first ? g_ya : g_yb) + (size_t)b * N_ * D_;
        const int nr = n0w + (lane >> 2);
        #pragma unroll
        for (int jj = 0; jj < 8; jj++) {
            int d = d0w + jj*8 + (lane & 3)*2;
            atomicAdd(&yo[nr*D_ + d],         acc[jj][0]);
            atomicAdd(&yo[nr*D_ + d + 1],     acc[jj][1]);
            atomicAdd(&yo[(nr+8)*D_ + d],     acc[jj][2]);
            atomicAdd(&yo[(nr+8)*D_ + d + 1], acc[jj][3]);
        }
    }
}

// ---------------- launch ----------------------------------------------------
extern "C" void kernel_launch(void* const* d_in, const int* in_sizes, int n_in,
                              void* d_out, int out_size) {
    (void)in_sizes; (void)n_in; (void)out_size;
    const float* x = (const float*)d_in[0];
    const float* W = (const float*)d_in[1];
    float* out = (float*)d_out;

    cudaFuncSetAttribute(capsule_kernel, cudaFuncAttributeMaxDynamicSharedMemorySize, CAPS_SMEM);
    cudaFuncSetAttribute(pass_kernel,    cudaFuncAttributeMaxDynamicSharedMemorySize, PASS_SMEM);

    zero_kernel<<<(B_*N_*D_ + 255) / 256, 256>>>();
    reduce_x_kernel<<<B_*8, 256>>>(x);                                  // y0 + split-bf16 x

    capsule_kernel<<<dim3(N_, B_/8), 256, CAPS_SMEM>>>(W, 0, nullptr, 1); // v0, p0
    pass_kernel<<<B_*CHUNKS, TPB, PASS_SMEM>>>(1);                        // iter1 -> g_ya, logits
    capsule_kernel<<<dim3(N_, B_/8), 256, CAPS_SMEM>>>(W, 1, nullptr, 1); // v1, p1
    pass_kernel<<<B_*CHUNKS, TPB, PASS_SMEM>>>(0);                        // iter2 -> g_yb
    capsule_kernel<<<dim3(N_, B_/8), 256, CAPS_SMEM>>>(W, 2, out, 0);     // v2 -> d_out
}

// round 10
// speedup vs baseline: 1.3876x; 1.0811x over previous
#include <cuda_runtime.h>
#include <cuda_bf16.h>
#include <math.h>
#include <stdint.h>

// Problem constants
#define B_  32
#define S_  1024
#define D_  256
#define N_  32
#define C_  64
#define M_  (B_*S_)

// pass kernel tiling (tensor-core version)
#define SCH 32                // s-values per block
#define CHUNKS (S_/SCH)       // 32
#define TPB 256               // 8 warps
#define XPB 528               // x smem row pitch BYTES (264 bf16; 33 x 16B, odd)
#define PPB 528               // p smem row pitch bytes
#define CTPB 80               // cT row pitch bytes (40 bf16; 5 x 16B, odd)
#define CPAD 36               // agree fp32 row stride (floats)

// smem byte offsets
#define O_XH  0
#define O_XL  (O_XH + SCH*XPB)       // 16896
#define O_PH  (O_XL + SCH*XPB)       // 33792
#define O_PL  (O_PH + N_*PPB)        // 50688
#define O_CTH (O_PL + N_*PPB)        // 67584
#define O_CTL (O_CTH + N_*CTPB)      // 70144
#define O_CS  (O_CTL + N_*CTPB)      // 72704
#define PASS_SMEM (O_CS + SCH*CPAD*4)// 77312 B -> 3 CTAs/SM (3x = 231936 <= 233472)

#define WPAD 65               // W smem row stride (capsule)
#define CAPS_SMEM  ((D_*WPAD + 8*D_ + 8*C_ + 8*C_) * 4)   // 78848 B

// ---------------- scratch (device globals; no runtime allocation) ----------
__device__ float          g_y0[B_*D_];        // (1/N) * sum_s x
__device__ float          g_ya[B_*N_*D_];     // y for iter1
__device__ float          g_yb[B_*N_*D_];     // y for iter2
__device__ float          g_v [B_*N_*C_];
__device__ float          g_logits[B_*S_*N_];
__device__ __nv_bfloat16  g_xhi[(size_t)M_*D_];
__device__ __nv_bfloat16  g_xlo[(size_t)M_*D_];
__device__ __nv_bfloat16  g_phi[B_*N_*D_];
__device__ __nv_bfloat16  g_plo[B_*N_*D_];

// ---------------- PTX helpers ----------------------------------------------
__device__ __forceinline__ uint32_t smem_u32(const void* p) {
    uint32_t a;
    asm("{ .reg .u64 t; cvta.to.shared.u64 t, %1; cvt.u32.u64 %0, t; }" : "=r"(a) : "l"(p));
    return a;
}
#define LDM_X4(r0,r1,r2,r3,a) \
    asm volatile("ldmatrix.sync.aligned.m8n8.x4.shared.b16 {%0,%1,%2,%3}, [%4];" \
        : "=r"(r0),"=r"(r1),"=r"(r2),"=r"(r3) : "r"(a))
#define LDM_X2(r0,r1,a) \
    asm volatile("ldmatrix.sync.aligned.m8n8.x2.shared.b16 {%0,%1}, [%2];" \
        : "=r"(r0),"=r"(r1) : "r"(a))
#define LDM_X4T(r0,r1,r2,r3,a) \
    asm volatile("ldmatrix.sync.aligned.m8n8.x4.trans.shared.b16 {%0,%1,%2,%3}, [%4];" \
        : "=r"(r0),"=r"(r1),"=r"(r2),"=r"(r3) : "r"(a))
__device__ __forceinline__ void mma_bf16(float* c, uint32_t a0, uint32_t a1, uint32_t a2,
                                         uint32_t a3, uint32_t b0, uint32_t b1) {
    asm volatile(
        "mma.sync.aligned.m16n8k16.row.col.f32.bf16.bf16.f32 "
        "{%0,%1,%2,%3}, {%4,%5,%6,%7}, {%8,%9}, {%0,%1,%2,%3};"
        : "+f"(c[0]), "+f"(c[1]), "+f"(c[2]), "+f"(c[3])
        : "r"(a0), "r"(a1), "r"(a2), "r"(a3), "r"(b0), "r"(b1));
}

// ---------------- zero ------------------------------------------------------
__global__ void zero_kernel() {
    int i = blockIdx.x * blockDim.x + threadIdx.x;
    if (i < B_*D_) g_y0[i] = 0.f;
    if (i < B_*N_*D_) { g_ya[i] = 0.f; g_yb[i] = 0.f; }
}

// ---------------- y0 = (1/N) sum_s x ; also emit split-bf16 x (vectorized) --
__global__ __launch_bounds__(256) void reduce_x_kernel(const float* __restrict__ x) {
    __shared__ float sred[256*4];
    const int b  = blockIdx.x >> 3;     // 32
    const int sg = blockIdx.x & 7;      // 8 groups x 128 s
    const int t  = threadIdx.x;
    const int q  = t & 63;              // d-quad: d = 4q
    const int rg = t >> 6;              // row-group 0..3
    const size_t rowbase = (size_t)b * S_ + sg * 128;

    float4 a = make_float4(0.f, 0.f, 0.f, 0.f);
    #pragma unroll 4
    for (int it = 0; it < 32; it++) {
        const int s = it*4 + rg;
        const size_t o = (rowbase + s) * D_ + 4*q;
        const float4 v = *(const float4*)(x + o);
        __nv_bfloat162 h01 = __float22bfloat162_rn(make_float2(v.x, v.y));
        __nv_bfloat162 h23 = __float22bfloat162_rn(make_float2(v.z, v.w));
        __nv_bfloat162 l01 = __float22bfloat162_rn(make_float2(
            v.x - __bfloat162float(h01.x), v.y - __bfloat162float(h01.y)));
        __nv_bfloat162 l23 = __float22bfloat162_rn(make_float2(
            v.z - __bfloat162float(h23.x), v.w - __bfloat162float(h23.y)));
        __nv_bfloat162* dh = (__nv_bfloat162*)(g_xhi + o);
        __nv_bfloat162* dl = (__nv_bfloat162*)(g_xlo + o);
        dh[0] = h01; dh[1] = h23;
        dl[0] = l01; dl[1] = l23;
        a.x += v.x; a.y += v.y; a.z += v.z; a.w += v.w;
    }
    *(float4*)&sred[t*4] = a;
    __syncthreads();
    if (t < 64) {
        float4 r0 = *(const float4*)&sred[t*4];
        float4 r1 = *(const float4*)&sred[(t+64)*4];
        float4 r2 = *(const float4*)&sred[(t+128)*4];
        float4 r3 = *(const float4*)&sred[(t+192)*4];
        const float sc = 1.0f / (float)N_;
        atomicAdd(&g_y0[b*D_ + 4*t + 0], (r0.x+r1.x+r2.x+r3.x)*sc);
        atomicAdd(&g_y0[b*D_ + 4*t + 1], (r0.y+r1.y+r2.y+r3.y)*sc);
        atomicAdd(&g_y0[b*D_ + 4*t + 2], (r0.z+r1.z+r2.z+r3.z)*sc);
        atomicAdd(&g_y0[b*D_ + 4*t + 3], (r0.w+r1.w+r2.w+r3.w)*sc);
    }
}

// ---------------- capsule: s = y@W, v = squash(s), p = W@v (split-bf16) -----
__global__ __launch_bounds__(256) void capsule_kernel(const float* __restrict__ W,
                                                      int ysel, float* __restrict__ vout_ext,
                                                      int compute_p) {
    extern __shared__ float sm[];
    float* sW = sm;                 // [D_][WPAD]
    float* sy = sW + D_*WPAD;       // [8][D_]
    float* ss = sy + 8*D_;          // [8][C_]
    float* sv = ss + 8*C_;          // [8][C_]

    const int n  = blockIdx.x;
    const int b0 = blockIdx.y * 8;
    const int t  = threadIdx.x;

    const float* Wn = W + (size_t)n * D_ * C_;
    for (int i = t; i < D_*C_; i += 256) {
        int d = i >> 6, c = i & 63;
        sW[d*WPAD + c] = Wn[i];
    }
    const float* ysrc = (ysel == 0) ? g_y0 : (ysel == 1) ? g_ya : g_yb;
    for (int i = t; i < 8*D_; i += 256) {
        int bb = i >> 8, d = i & 255;
        sy[bb*D_ + d] = (ysel == 0) ? ysrc[(b0+bb)*D_ + d]
                                    : ysrc[((size_t)(b0+bb)*N_ + n)*D_ + d];
    }
    __syncthreads();

    {
        const int c = t & 63, bt = t >> 6;
        float s0 = 0.f, s1 = 0.f;
        const float* y0r = sy + (bt*2+0)*D_;
        const float* y1r = sy + (bt*2+1)*D_;
        #pragma unroll 4
        for (int d = 0; d < D_; d++) {
            float w = sW[d*WPAD + c];
            s0 += y0r[d] * w;
            s1 += y1r[d] * w;
        }
        ss[(bt*2+0)*C_ + c] = s0;
        ss[(bt*2+1)*C_ + c] = s1;
    }
    __syncthreads();

    const int wid = t >> 5, lane = t & 31;
    {
        float a0 = ss[wid*C_ + lane];
        float a1 = ss[wid*C_ + 32 + lane];
        float sq = a0*a0 + a1*a1;
        #pragma unroll
        for (int o = 16; o > 0; o >>= 1) sq += __shfl_xor_sync(0xffffffffu, sq, o);
        float sc = (sq / (1.f + sq)) * rsqrtf(sq + 1e-8f);
        float v0 = a0 * sc, v1 = a1 * sc;
        sv[wid*C_ + lane]      = v0;
        sv[wid*C_ + 32 + lane] = v1;
        float* vo = (vout_ext ? vout_ext : g_v) + ((size_t)(b0+wid)*N_ + n)*C_;
        vo[lane]      = v0;
        vo[32 + lane] = v1;
    }
    __syncthreads();

    if (compute_p) {
        const int b = t >> 5, dl = t & 31;
        const float* vb = sv + b*C_;
        #pragma unroll
        for (int dd = 0; dd < 8; dd++) {
            int d = dd*32 + dl;
            const float* wr = sW + d*WPAD;
            float acc = 0.f;
            #pragma unroll
            for (int cc = 0; cc < C_; cc++) acc += wr[cc] * vb[cc];
            size_t o = ((size_t)(b0+b)*N_ + n)*D_ + d;
            __nv_bfloat16 h = __float2bfloat16(acc);
            g_phi[o] = h;
            g_plo[o] = __float2bfloat16(acc - __bfloat162float(h));
        }
    }
}

// ---------------- fused routing pass (tensor cores) --------------------------
// grid = B_*CHUNKS (1024), 256 threads, 3 CTAs/SM.
__global__ __launch_bounds__(TPB, 3) void pass_kernel(int first) {
    extern __shared__ char smc[];
    char* xh  = smc + O_XH;
    char* xl  = smc + O_XL;
    char* ph  = smc + O_PH;
    char* pl  = smc + O_PL;
    char* cth = smc + O_CTH;
    char* ctl = smc + O_CTL;
    float* cS = (float*)(smc + O_CS);

    const int t = threadIdx.x, wid = t >> 5, lane = t & 31;
    const int b  = blockIdx.x >> 5;
    const int ch = blockIdx.x & 31;
    const int s0 = ch * SCH;

    // load x planes (32 rows x 512B) and p planes (32 rows x 512B), coalesced
    {
        const uint4* sh = (const uint4*)(g_xhi + ((size_t)(b*S_ + s0)) * D_);
        const uint4* sl = (const uint4*)(g_xlo + ((size_t)(b*S_ + s0)) * D_);
        #pragma unroll
        for (int i = t; i < SCH*32; i += TPB) {
            int s = i >> 5, q = i & 31;
            *(uint4*)(xh + s*XPB + q*16) = sh[i];
            *(uint4*)(xl + s*XPB + q*16) = sl[i];
        }
        const uint4* qh = (const uint4*)(g_phi + (size_t)b * N_ * D_);
        const uint4* ql = (const uint4*)(g_plo + (size_t)b * N_ * D_);
        #pragma unroll
        for (int i = t; i < N_*32; i += TPB) {
            int n = i >> 5, q = i & 31;
            *(uint4*)(ph + n*PPB + q*16) = qh[i];
            *(uint4*)(pl + n*PPB + q*16) = ql[i];
        }
    }
    __syncthreads();

    // phase 2: agree = X (32s x 256k) @ P^T -> warp tile m16(s) x n8(n), full K
    // 3 independent accumulators break the hi*hi/hi*lo/lo*hi dependency chain.
    {
        const int pm = wid & 1, pn = wid >> 1;       // 2 x 4 warp grid
        const int s0w = pm * 16, n0w = pn * 8;
        const uint32_t aH = smem_u32(xh) + (s0w + (lane & 15))*XPB + (lane >> 4)*16;
        const uint32_t aL = smem_u32(xl) + (s0w + (lane & 15))*XPB + (lane >> 4)*16;
        const uint32_t bH = smem_u32(ph) + (n0w + (lane & 7))*PPB + ((lane >> 3) & 1)*16;
        const uint32_t bL = smem_u32(pl) + (n0w + (lane & 7))*PPB + ((lane >> 3) & 1)*16;
        float c1[4] = {0.f,0.f,0.f,0.f};
        float c2[4] = {0.f,0.f,0.f,0.f};
        float c3[4] = {0.f,0.f,0.f,0.f};
        #pragma unroll
        for (int k = 0; k < 16; k++) {
            uint32_t ah0,ah1,ah2,ah3, al0,al1,al2,al3, bh0,bh1, bl0,bl1;
            LDM_X4(ah0,ah1,ah2,ah3, aH + k*32);
            LDM_X4(al0,al1,al2,al3, aL + k*32);
            LDM_X2(bh0,bh1, bH + k*32);
            LDM_X2(bl0,bl1, bL + k*32);
            mma_bf16(c1, ah0,ah1,ah2,ah3, bh0,bh1);   // hi*hi
            mma_bf16(c2, ah0,ah1,ah2,ah3, bl0,bl1);   // hi*lo
            mma_bf16(c3, al0,al1,al2,al3, bh0,bh1);   // lo*hi
        }
        const int sr = s0w + (lane >> 2), nc = n0w + (lane & 3)*2;
        cS[sr*CPAD + nc]         = c1[0] + c2[0] + c3[0];
        cS[sr*CPAD + nc + 1]     = c1[1] + c2[1] + c3[1];
        cS[(sr+8)*CPAD + nc]     = c1[2] + c2[2] + c3[2];
        cS[(sr+8)*CPAD + nc + 1] = c1[3] + c2[3] + c3[3];
    }
    __syncthreads();

    // softmax over n per s-row; write split-bf16 transposed coefs cT[n][s]
    {
        #pragma unroll
        for (int r = 0; r < 4; r++) {
            int s = wid*4 + r;
            float lg = cS[s*CPAD + lane];
            size_t li = ((size_t)b * S_ + s0 + s) * N_ + lane;
            if (first) g_logits[li] = lg;
            else       lg += g_logits[li];
            float mx = lg;
            #pragma unroll
            for (int o = 16; o > 0; o >>= 1) mx = fmaxf(mx, __shfl_xor_sync(0xffffffffu, mx, o));
            float e = expf(lg - mx);
            float sum = e;
            #pragma unroll
            for (int o = 16; o > 0; o >>= 1) sum += __shfl_xor_sync(0xffffffffu, sum, o);
            float cv = e / sum;
            __nv_bfloat16 hh = __float2bfloat16(cv);
            *(__nv_bfloat16*)(cth + lane*CTPB + s*2) = hh;
            *(__nv_bfloat16*)(ctl + lane*CTPB + s*2) =
                __float2bfloat16(cv - __bfloat162float(hh));
        }
    }
    __syncthreads();

    // phase 3: y = C^T (32n x 32k(s)) @ X (32s x 256d) -> warp m16(n) x 64d
    {
        const int wm = wid & 1, wd = wid >> 1;       // 2 x 4 warp grid
        const int n0w = wm * 16, d0w = wd * 64;
        const uint32_t aH = smem_u32(cth) + (n0w + (lane & 15))*CTPB + (lane >> 4)*16;
        const uint32_t aL = smem_u32(ctl) + (n0w + (lane & 15))*CTPB + (lane >> 4)*16;
        const int part  = lane >> 3;
        const int brow  = (part & 1)*8 + (lane & 7);  // s-row within 16
        const int bcolb = (part >> 1)*16;             // byte offset for d+8 half
        float acc[8][4];
        #pragma unroll
        for (int i = 0; i < 8; i++)
            #pragma unroll
            for (int j = 0; j < 4; j++) acc[i][j] = 0.f;

        #pragma unroll
        for (int ks = 0; ks < 2; ks++) {
            uint32_t ah0,ah1,ah2,ah3, al0,al1,al2,al3;
            LDM_X4(ah0,ah1,ah2,ah3, aH + ks*32);
            LDM_X4(al0,al1,al2,al3, aL + ks*32);
            #pragma unroll
            for (int j = 0; j < 4; j++) {
                const int dd = d0w + j*16;
                const uint32_t xb  = smem_u32(xh) + (ks*16 + brow)*XPB + dd*2 + bcolb;
                const uint32_t xlb = smem_u32(xl) + (ks*16 + brow)*XPB + dd*2 + bcolb;
                uint32_t bh0,bh1,bh2,bh3, bl0,bl1,bl2,bl3;
                LDM_X4T(bh0,bh1,bh2,bh3, xb);
                LDM_X4T(bl0,bl1,bl2,bl3, xlb);
                mma_bf16(acc[2*j],   ah0,ah1,ah2,ah3, bh0,bh1);
                mma_bf16(acc[2*j],   ah0,ah1,ah2,ah3, bl0,bl1);
                mma_bf16(acc[2*j],   al0,al1,al2,al3, bh0,bh1);
                mma_bf16(acc[2*j+1], ah0,ah1,ah2,ah3, bh2,bh3);
                mma_bf16(acc[2*j+1], ah0,ah1,ah2,ah3, bl2,bl3);
                mma_bf16(acc[2*j+1], al0,al1,al2,al3, bh2,bh3);
            }
        }
        float* yo = (first ? g_ya : g_yb) + (size_t)b * N_ * D_;
        const int nr = n0w + (lane >> 2);
        #pragma unroll
        for (int jj = 0; jj < 8; jj++) {
            int d = d0w + jj*8 + (lane & 3)*2;
            atomicAdd(&yo[nr*D_ + d],         acc[jj][0]);
            atomicAdd(&yo[nr*D_ + d + 1],     acc[jj][1]);
            atomicAdd(&yo[(nr+8)*D_ + d],     acc[jj][2]);
            atomicAdd(&yo[(nr+8)*D_ + d + 1], acc[jj][3]);
        }
    }
}

// ---------------- launch ----------------------------------------------------
extern "C" void kernel_launch(void* const* d_in, const int* in_sizes, int n_in,
                              void* d_out, int out_size) {
    (void)in_sizes; (void)n_in; (void)out_size;
    const float* x = (const float*)d_in[0];
    const float* W = (const float*)d_in[1];
    float* out = (float*)d_out;

    cudaFuncSetAttribute(capsule_kernel, cudaFuncAttributeMaxDynamicSharedMemorySize, CAPS_SMEM);
    cudaFuncSetAttribute(pass_kernel,    cudaFuncAttributeMaxDynamicSharedMemorySize, PASS_SMEM);

    zero_kernel<<<(B_*N_*D_ + 255) / 256, 256>>>();
    reduce_x_kernel<<<B_*8, 256>>>(x);                                  // y0 + split-bf16 x

    capsule_kernel<<<dim3(N_, B_/8), 256, CAPS_SMEM>>>(W, 0, nullptr, 1); // v0, p0
    pass_kernel<<<B_*CHUNKS, TPB, PASS_SMEM>>>(1);                        // iter1 -> g_ya, logits
    capsule_kernel<<<dim3(N_, B_/8), 256, CAPS_SMEM>>>(W, 1, nullptr, 1); // v1, p1
    pass_kernel<<<B_*CHUNKS, TPB, PASS_SMEM>>>(0);                        // iter2 -> g_yb
    capsule_kernel<<<dim3(N_, B_/8), 256, CAPS_SMEM>>>(W, 2, out, 0);     // v2 -> d_out
}

// round 11
// speedup vs baseline: 1.5054x; 1.0849x over previous
#include <cuda_runtime.h>
#include <cuda_bf16.h>
#include <math.h>
#include <stdint.h>

// Problem constants
#define B_  32
#define S_  1024
#define D_  256
#define N_  32
#define C_  64
#define M_  (B_*S_)

// pass kernel tiling (tensor-core version)
#define SCH 32                // s-values per block
#define CHUNKS (S_/SCH)       // 32
#define TPB 256               // 8 warps
#define XPB 528               // x smem row pitch BYTES (264 bf16; 33 x 16B, odd)
#define PPB 528               // p smem row pitch bytes
#define CTPB 80               // cT row pitch bytes (40 bf16; 5 x 16B, odd)
#define CPAD 36               // agree fp32 row stride (floats)

// smem byte offsets; cS (4608 B) aliases cth+ctl (5120 B) — live ranges disjoint
#define O_XH  0
#define O_XL  (O_XH + SCH*XPB)       // 16896
#define O_PH  (O_XL + SCH*XPB)       // 33792
#define O_PL  (O_PH + N_*PPB)        // 50688
#define O_CS  (O_PL + N_*PPB)        // 67584
#define O_CTH O_CS                   // 67584 (alias)
#define O_CTL (O_CTH + N_*CTPB)      // 70144
#define PASS_SMEM (O_CTL + N_*CTPB)  // 72704 B -> 3 CTAs/SM (218112 total)

#define WPAD 65               // W smem row stride (capsule)
#define CAPS_SMEM  ((D_*WPAD + 8*D_ + 8*C_ + 8*C_) * 4)   // 78848 B

// ---------------- scratch (device globals; no runtime allocation) ----------
__device__ float          g_y0p[8*B_*D_];     // per-chunk partials of (1/N) sum_s x
__device__ float          g_ya[B_*N_*D_];     // y for iter1
__device__ float          g_yb[B_*N_*D_];     // y for iter2
__device__ float          g_v [B_*N_*C_];
__device__ float          g_logits[B_*S_*N_];
__device__ __nv_bfloat16  g_xhi[(size_t)M_*D_];
__device__ __nv_bfloat16  g_xlo[(size_t)M_*D_];
__device__ __nv_bfloat16  g_phi[B_*N_*D_];
__device__ __nv_bfloat16  g_plo[B_*N_*D_];

// ---------------- PTX helpers ----------------------------------------------
__device__ __forceinline__ uint32_t smem_u32(const void* p) {
    uint32_t a;
    asm("{ .reg .u64 t; cvta.to.shared.u64 t, %1; cvt.u32.u64 %0, t; }" : "=r"(a) : "l"(p));
    return a;
}
#define LDM_X4(r0,r1,r2,r3,a) \
    asm volatile("ldmatrix.sync.aligned.m8n8.x4.shared.b16 {%0,%1,%2,%3}, [%4];" \
        : "=r"(r0),"=r"(r1),"=r"(r2),"=r"(r3) : "r"(a))
#define LDM_X2(r0,r1,a) \
    asm volatile("ldmatrix.sync.aligned.m8n8.x2.shared.b16 {%0,%1}, [%2];" \
        : "=r"(r0),"=r"(r1) : "r"(a))
#define LDM_X4T(r0,r1,r2,r3,a) \
    asm volatile("ldmatrix.sync.aligned.m8n8.x4.trans.shared.b16 {%0,%1,%2,%3}, [%4];" \
        : "=r"(r0),"=r"(r1),"=r"(r2),"=r"(r3) : "r"(a))
__device__ __forceinline__ void mma_bf16(float* c, uint32_t a0, uint32_t a1, uint32_t a2,
                                         uint32_t a3, uint32_t b0, uint32_t b1) {
    asm volatile(
        "mma.sync.aligned.m16n8k16.row.col.f32.bf16.bf16.f32 "
        "{%0,%1,%2,%3}, {%4,%5,%6,%7}, {%8,%9}, {%0,%1,%2,%3};"
        : "+f"(c[0]), "+f"(c[1]), "+f"(c[2]), "+f"(c[3])
        : "r"(a0), "r"(a1), "r"(a2), "r"(a3), "r"(b0), "r"(b1));
}
__device__ __forceinline__ void red_add_v2(float* p, float a, float b) {
    asm volatile("red.global.add.v2.f32 [%0], {%1, %2};"
        :: "l"(__cvta_generic_to_global(p)), "f"(a), "f"(b) : "memory");
}

// ---------------- y0 partials + split-bf16 x emit + ya/yb zeroing -----------
__global__ __launch_bounds__(256) void reduce_x_kernel(const float* __restrict__ x) {
    __shared__ float sred[256*4];
    const int b  = blockIdx.x >> 3;     // 32
    const int sg = blockIdx.x & 7;      // 8 groups x 128 s
    const int t  = threadIdx.x;
    const int q  = t & 63;              // d-quad: d = 4q
    const int rg = t >> 6;              // row-group 0..3
    const size_t rowbase = (size_t)b * S_ + sg * 128;

    // zero 1/256 slice of g_ya and g_yb (no ordering hazard: pure stores)
    {
        float4 z = make_float4(0.f, 0.f, 0.f, 0.f);
        ((float4*)g_ya)[blockIdx.x*256 + t] = z;
        ((float4*)g_yb)[blockIdx.x*256 + t] = z;
    }

    float4 a = make_float4(0.f, 0.f, 0.f, 0.f);
    #pragma unroll 4
    for (int it = 0; it < 32; it++) {
        const int s = it*4 + rg;
        const size_t o = (rowbase + s) * D_ + 4*q;
        const float4 v = *(const float4*)(x + o);
        __nv_bfloat162 h01 = __float22bfloat162_rn(make_float2(v.x, v.y));
        __nv_bfloat162 h23 = __float22bfloat162_rn(make_float2(v.z, v.w));
        __nv_bfloat162 l01 = __float22bfloat162_rn(make_float2(
            v.x - __bfloat162float(h01.x), v.y - __bfloat162float(h01.y)));
        __nv_bfloat162 l23 = __float22bfloat162_rn(make_float2(
            v.z - __bfloat162float(h23.x), v.w - __bfloat162float(h23.y)));
        __nv_bfloat162* dh = (__nv_bfloat162*)(g_xhi + o);
        __nv_bfloat162* dl = (__nv_bfloat162*)(g_xlo + o);
        dh[0] = h01; dh[1] = h23;
        dl[0] = l01; dl[1] = l23;
        a.x += v.x; a.y += v.y; a.z += v.z; a.w += v.w;
    }
    *(float4*)&sred[t*4] = a;
    __syncthreads();
    if (t < 64) {
        float4 r0 = *(const float4*)&sred[t*4];
        float4 r1 = *(const float4*)&sred[(t+64)*4];
        float4 r2 = *(const float4*)&sred[(t+128)*4];
        float4 r3 = *(const float4*)&sred[(t+192)*4];
        const float sc = 1.0f / (float)N_;
        float4 o = make_float4((r0.x+r1.x+r2.x+r3.x)*sc, (r0.y+r1.y+r2.y+r3.y)*sc,
                               (r0.z+r1.z+r2.z+r3.z)*sc, (r0.w+r1.w+r2.w+r3.w)*sc);
        *(float4*)&g_y0p[(sg*B_ + b)*D_ + 4*t] = o;
    }
}

// ---------------- capsule: s = y@W, v = squash(s), p = W@v (split-bf16) -----
__global__ __launch_bounds__(256) void capsule_kernel(const float* __restrict__ W,
                                                      int ysel, float* __restrict__ vout_ext,
                                                      int compute_p) {
    extern __shared__ float sm[];
    float* sW = sm;                 // [D_][WPAD]
    float* sy = sW + D_*WPAD;       // [8][D_]
    float* ss = sy + 8*D_;          // [8][C_]
    float* sv = ss + 8*C_;          // [8][C_]

    const int n  = blockIdx.x;
    const int b0 = blockIdx.y * 8;
    const int t  = threadIdx.x;

    const float* Wn = W + (size_t)n * D_ * C_;
    for (int i = t; i < D_*C_; i += 256) {
        int d = i >> 6, c = i & 63;
        sW[d*WPAD + c] = Wn[i];
    }
    for (int i = t; i < 8*D_; i += 256) {
        int bb = i >> 8, d = i & 255;
        if (ysel == 0) {
            float a = 0.f;
            #pragma unroll
            for (int k = 0; k < 8; k++) a += g_y0p[(k*B_ + b0+bb)*D_ + d];
            sy[bb*D_ + d] = a;
        } else {
            const float* ysrc = (ysel == 1) ? g_ya : g_yb;
            sy[bb*D_ + d] = ysrc[((size_t)(b0+bb)*N_ + n)*D_ + d];
        }
    }
    __syncthreads();

    {
        const int c = t & 63, bt = t >> 6;
        float s0 = 0.f, s1 = 0.f;
        const float* y0r = sy + (bt*2+0)*D_;
        const float* y1r = sy + (bt*2+1)*D_;
        #pragma unroll 4
        for (int d = 0; d < D_; d++) {
            float w = sW[d*WPAD + c];
            s0 += y0r[d] * w;
            s1 += y1r[d] * w;
        }
        ss[(bt*2+0)*C_ + c] = s0;
        ss[(bt*2+1)*C_ + c] = s1;
    }
    __syncthreads();

    const int wid = t >> 5, lane = t & 31;
    {
        float a0 = ss[wid*C_ + lane];
        float a1 = ss[wid*C_ + 32 + lane];
        float sq = a0*a0 + a1*a1;
        #pragma unroll
        for (int o = 16; o > 0; o >>= 1) sq += __shfl_xor_sync(0xffffffffu, sq, o);
        float sc = (sq / (1.f + sq)) * rsqrtf(sq + 1e-8f);
        float v0 = a0 * sc, v1 = a1 * sc;
        sv[wid*C_ + lane]      = v0;
        sv[wid*C_ + 32 + lane] = v1;
        float* vo = (vout_ext ? vout_ext : g_v) + ((size_t)(b0+wid)*N_ + n)*C_;
        vo[lane]      = v0;
        vo[32 + lane] = v1;
    }
    __syncthreads();

    if (compute_p) {
        const int b = t >> 5, dl = t & 31;
        const float* vb = sv + b*C_;
        #pragma unroll
        for (int dd = 0; dd < 8; dd++) {
            int d = dd*32 + dl;
            const float* wr = sW + d*WPAD;
            float acc = 0.f;
            #pragma unroll
            for (int cc = 0; cc < C_; cc++) acc += wr[cc] * vb[cc];
            size_t o = ((size_t)(b0+b)*N_ + n)*D_ + d;
            __nv_bfloat16 h = __float2bfloat16(acc);
            g_phi[o] = h;
            g_plo[o] = __float2bfloat16(acc - __bfloat162float(h));
        }
    }
}

// ---------------- fused routing pass (tensor cores) --------------------------
// grid = B_*CHUNKS (1024), 256 threads, 3 CTAs/SM.
__global__ __launch_bounds__(TPB, 3) void pass_kernel(int first) {
    extern __shared__ char smc[];
    char* xh  = smc + O_XH;
    char* xl  = smc + O_XL;
    char* ph  = smc + O_PH;
    char* pl  = smc + O_PL;
    char* cth = smc + O_CTH;
    char* ctl = smc + O_CTL;
    float* cS = (float*)(smc + O_CS);   // aliases cth/ctl; live ranges disjoint

    const int t = threadIdx.x, wid = t >> 5, lane = t & 31;
    const int b  = blockIdx.x >> 5;
    const int ch = blockIdx.x & 31;
    const int s0 = ch * SCH;

    // load x planes (32 rows x 512B) and p planes (32 rows x 512B), coalesced
    {
        const uint4* sh = (const uint4*)(g_xhi + ((size_t)(b*S_ + s0)) * D_);
        const uint4* sl = (const uint4*)(g_xlo + ((size_t)(b*S_ + s0)) * D_);
        #pragma unroll
        for (int i = t; i < SCH*32; i += TPB) {
            int s = i >> 5, q = i & 31;
            *(uint4*)(xh + s*XPB + q*16) = sh[i];
            *(uint4*)(xl + s*XPB + q*16) = sl[i];
        }
        const uint4* qh = (const uint4*)(g_phi + (size_t)b * N_ * D_);
        const uint4* ql = (const uint4*)(g_plo + (size_t)b * N_ * D_);
        #pragma unroll
        for (int i = t; i < N_*32; i += TPB) {
            int n = i >> 5, q = i & 31;
            *(uint4*)(ph + n*PPB + q*16) = qh[i];
            *(uint4*)(pl + n*PPB + q*16) = ql[i];
        }
    }
    __syncthreads();

    // phase 2: agree = X (32s x 256k) @ P^T -> warp tile m16(s) x n8(n), full K
    {
        const int pm = wid & 1, pn = wid >> 1;       // 2 x 4 warp grid
        const int s0w = pm * 16, n0w = pn * 8;
        const uint32_t aH = smem_u32(xh) + (s0w + (lane & 15))*XPB + (lane >> 4)*16;
        const uint32_t aL = smem_u32(xl) + (s0w + (lane & 15))*XPB + (lane >> 4)*16;
        const uint32_t bH = smem_u32(ph) + (n0w + (lane & 7))*PPB + ((lane >> 3) & 1)*16;
        const uint32_t bL = smem_u32(pl) + (n0w + (lane & 7))*PPB + ((lane >> 3) & 1)*16;
        float c1[4] = {0.f,0.f,0.f,0.f};
        float c2[4] = {0.f,0.f,0.f,0.f};
        float c3[4] = {0.f,0.f,0.f,0.f};
        #pragma unroll
        for (int k = 0; k < 16; k++) {
            uint32_t ah0,ah1,ah2,ah3, al0,al1,al2,al3, bh0,bh1, bl0,bl1;
            LDM_X4(ah0,ah1,ah2,ah3, aH + k*32);
            LDM_X4(al0,al1,al2,al3, aL + k*32);
            LDM_X2(bh0,bh1, bH + k*32);
            LDM_X2(bl0,bl1, bL + k*32);
            mma_bf16(c1, ah0,ah1,ah2,ah3, bh0,bh1);   // hi*hi
            mma_bf16(c2, ah0,ah1,ah2,ah3, bl0,bl1);   // hi*lo
            mma_bf16(c3, al0,al1,al2,al3, bh0,bh1);   // lo*hi
        }
        const int sr = s0w + (lane >> 2), nc = n0w + (lane & 3)*2;
        cS[sr*CPAD + nc]         = c1[0] + c2[0] + c3[0];
        cS[sr*CPAD + nc + 1]     = c1[1] + c2[1] + c3[1];
        cS[(sr+8)*CPAD + nc]     = c1[2] + c2[2] + c3[2];
        cS[(sr+8)*CPAD + nc + 1] = c1[3] + c2[3] + c3[3];
    }
    __syncthreads();

    // softmax over n per s-row, split into read -> barrier -> compute+write
    // so cth/ctl may alias cS.
    {
        float lg[4];
        #pragma unroll
        for (int r = 0; r < 4; r++) {
            int s = wid*4 + r;
            lg[r] = cS[s*CPAD + lane];
            size_t li = ((size_t)b * S_ + s0 + s) * N_ + lane;
            if (first) g_logits[li] = lg[r];
            else       lg[r] += g_logits[li];
        }
        __syncthreads();   // all cS reads complete before aliased writes
        #pragma unroll
        for (int r = 0; r < 4; r++) {
            int s = wid*4 + r;
            float v = lg[r];
            float mx = v;
            #pragma unroll
            for (int o = 16; o > 0; o >>= 1) mx = fmaxf(mx, __shfl_xor_sync(0xffffffffu, mx, o));
            float e = expf(v - mx);
            float sum = e;
            #pragma unroll
            for (int o = 16; o > 0; o >>= 1) sum += __shfl_xor_sync(0xffffffffu, sum, o);
            float cv = e / sum;
            __nv_bfloat16 hh = __float2bfloat16(cv);
            *(__nv_bfloat16*)(cth + lane*CTPB + s*2) = hh;
            *(__nv_bfloat16*)(ctl + lane*CTPB + s*2) =
                __float2bfloat16(cv - __bfloat162float(hh));
        }
    }
    __syncthreads();

    // phase 3: y = C^T (32n x 32k(s)) @ X (32s x 256d) -> warp m16(n) x 64d
    {
        const int wm = wid & 1, wd = wid >> 1;       // 2 x 4 warp grid
        const int n0w = wm * 16, d0w = wd * 64;
        const uint32_t aH = smem_u32(cth) + (n0w + (lane & 15))*CTPB + (lane >> 4)*16;
        const uint32_t aL = smem_u32(ctl) + (n0w + (lane & 15))*CTPB + (lane >> 4)*16;
        const int part  = lane >> 3;
        const int brow  = (part & 1)*8 + (lane & 7);  // s-row within 16
        const int bcolb = (part >> 1)*16;             // byte offset for d+8 half
        float acc[8][4];
        #pragma unroll
        for (int i = 0; i < 8; i++)
            #pragma unroll
            for (int j = 0; j < 4; j++) acc[i][j] = 0.f;

        #pragma unroll
        for (int ks = 0; ks < 2; ks++) {
            uint32_t ah0,ah1,ah2,ah3, al0,al1,al2,al3;
            LDM_X4(ah0,ah1,ah2,ah3, aH + ks*32);
            LDM_X4(al0,al1,al2,al3, aL + ks*32);
            #pragma unroll
            for (int j = 0; j < 4; j++) {
                const int dd = d0w + j*16;
                const uint32_t xb  = smem_u32(xh) + (ks*16 + brow)*XPB + dd*2 + bcolb;
                const uint32_t xlb = smem_u32(xl) + (ks*16 + brow)*XPB + dd*2 + bcolb;
                uint32_t bh0,bh1,bh2,bh3, bl0,bl1,bl2,bl3;
                LDM_X4T(bh0,bh1,bh2,bh3, xb);
                LDM_X4T(bl0,bl1,bl2,bl3, xlb);
                mma_bf16(acc[2*j],   ah0,ah1,ah2,ah3, bh0,bh1);
                mma_bf16(acc[2*j],   ah0,ah1,ah2,ah3, bl0,bl1);
                mma_bf16(acc[2*j],   al0,al1,al2,al3, bh0,bh1);
                mma_bf16(acc[2*j+1], ah0,ah1,ah2,ah3, bh2,bh3);
                mma_bf16(acc[2*j+1], ah0,ah1,ah2,ah3, bl2,bl3);
                mma_bf16(acc[2*j+1], al0,al1,al2,al3, bh2,bh3);
            }
        }
        float* yo = (first ? g_ya : g_yb) + (size_t)b * N_ * D_;
        const int nr = n0w + (lane >> 2);
        #pragma unroll
        for (int jj = 0; jj < 8; jj++) {
            int d = d0w + jj*8 + (lane & 3)*2;
            red_add_v2(&yo[nr*D_ + d],     acc[jj][0], acc[jj][1]);
            red_add_v2(&yo[(nr+8)*D_ + d], acc[jj][2], acc[jj][3]);
        }
    }
}

// ---------------- launch ----------------------------------------------------
extern "C" void kernel_launch(void* const* d_in, const int* in_sizes, int n_in,
                              void* d_out, int out_size) {
    (void)in_sizes; (void)n_in; (void)out_size;
    const float* x = (const float*)d_in[0];
    const float* W = (const float*)d_in[1];
    float* out = (float*)d_out;

    cudaFuncSetAttribute(capsule_kernel, cudaFuncAttributeMaxDynamicSharedMemorySize, CAPS_SMEM);
    cudaFuncSetAttribute(pass_kernel,    cudaFuncAttributeMaxDynamicSharedMemorySize, PASS_SMEM);

    reduce_x_kernel<<<B_*8, 256>>>(x);                 // y0 partials + bf16 x + zero ya/yb

    capsule_kernel<<<dim3(N_, B_/8), 256, CAPS_SMEM>>>(W, 0, nullptr, 1); // v0, p0
    pass_kernel<<<B_*CHUNKS, TPB, PASS_SMEM>>>(1);                        // iter1 -> g_ya, logits
    capsule_kernel<<<dim3(N_, B_/8), 256, CAPS_SMEM>>>(W, 1, nullptr, 1); // v1, p1
    pass_kernel<<<B_*CHUNKS, TPB, PASS_SMEM>>>(0);                        // iter2 -> g_yb
    capsule_kernel<<<dim3(N_, B_/8), 256, CAPS_SMEM>>>(W, 2, out, 0);     // v2 -> d_out
}

// round 12
// speedup vs baseline: 1.8076x; 1.2007x over previous
#include <cuda_runtime.h>
#include <cuda_bf16.h>
#include <math.h>
#include <stdint.h>

// Problem constants
#define B_  32
#define S_  1024
#define D_  256
#define N_  32
#define C_  64
#define M_  (B_*S_)

// pass kernel tiling (tensor-core version)
#define SCH 32                // s-values per block
#define CHUNKS (S_/SCH)       // 32
#define TPB 256               // 8 warps
#define XPB 528               // x smem row pitch BYTES (264 bf16; 33 x 16B, odd)
#define PPB 528               // p smem row pitch bytes
#define CTPB 80               // cT row pitch bytes (40 bf16; 5 x 16B, odd)
#define CPAD 36               // agree fp32 row stride (floats)

// smem byte offsets; cS (4608 B) aliases cth+ctl (5120 B) — live ranges disjoint
#define O_XH  0
#define O_XL  (O_XH + SCH*XPB)       // 16896
#define O_PH  (O_XL + SCH*XPB)       // 33792
#define O_PL  (O_PH + N_*PPB)        // 50688
#define O_CS  (O_PL + N_*PPB)        // 67584
#define O_CTH O_CS                   // 67584 (alias)
#define O_CTL (O_CTH + N_*CTPB)      // 70144
#define PASS_SMEM (O_CTL + N_*CTPB)  // 72704 B -> 3 CTAs/SM (218112 total)

// capsule: 4 b's per block, 256 threads, grid (N_, B_/4) = 256 blocks
#define WPAD 68               // W smem row stride (floats); 17 float4/row
#define CB 4                  // b's per capsule block
#define CAPS_SMEM ((D_*WPAD + CB*D_ + CB*C_ + CB*C_) * 4)  // 75776 B

// ---------------- scratch (device globals; no runtime allocation) ----------
__device__ float          g_y0p[8*B_*D_];     // per-chunk partials of (1/N) sum_s x
__device__ float          g_ya[B_*N_*D_];     // y for iter1
__device__ float          g_yb[B_*N_*D_];     // y for iter2
__device__ float          g_v [B_*N_*C_];
__device__ float          g_logits[B_*S_*N_];
__device__ __nv_bfloat16  g_xhi[(size_t)M_*D_];
__device__ __nv_bfloat16  g_xlo[(size_t)M_*D_];
__device__ __nv_bfloat16  g_phi[B_*N_*D_];
__device__ __nv_bfloat16  g_plo[B_*N_*D_];

// ---------------- PTX helpers ----------------------------------------------
__device__ __forceinline__ uint32_t smem_u32(const void* p) {
    uint32_t a;
    asm("{ .reg .u64 t; cvta.to.shared.u64 t, %1; cvt.u32.u64 %0, t; }" : "=r"(a) : "l"(p));
    return a;
}
#define LDM_X4(r0,r1,r2,r3,a) \
    asm volatile("ldmatrix.sync.aligned.m8n8.x4.shared.b16 {%0,%1,%2,%3}, [%4];" \
        : "=r"(r0),"=r"(r1),"=r"(r2),"=r"(r3) : "r"(a))
#define LDM_X2(r0,r1,a) \
    asm volatile("ldmatrix.sync.aligned.m8n8.x2.shared.b16 {%0,%1}, [%2];" \
        : "=r"(r0),"=r"(r1) : "r"(a))
#define LDM_X4T(r0,r1,r2,r3,a) \
    asm volatile("ldmatrix.sync.aligned.m8n8.x4.trans.shared.b16 {%0,%1,%2,%3}, [%4];" \
        : "=r"(r0),"=r"(r1),"=r"(r2),"=r"(r3) : "r"(a))
__device__ __forceinline__ void mma_bf16(float* c, uint32_t a0, uint32_t a1, uint32_t a2,
                                         uint32_t a3, uint32_t b0, uint32_t b1) {
    asm volatile(
        "mma.sync.aligned.m16n8k16.row.col.f32.bf16.bf16.f32 "
        "{%0,%1,%2,%3}, {%4,%5,%6,%7}, {%8,%9}, {%0,%1,%2,%3};"
        : "+f"(c[0]), "+f"(c[1]), "+f"(c[2]), "+f"(c[3])
        : "r"(a0), "r"(a1), "r"(a2), "r"(a3), "r"(b0), "r"(b1));
}
__device__ __forceinline__ void red_add_v2(float* p, float a, float b) {
    asm volatile("red.global.add.v2.f32 [%0], {%1, %2};"
        :: "l"(__cvta_generic_to_global(p)), "f"(a), "f"(b) : "memory");
}
__device__ __forceinline__ void cp16(uint32_t dst, const void* src) {
    asm volatile("cp.async.cg.shared.global [%0], [%1], 16;"
        :: "r"(dst), "l"(__cvta_generic_to_global(src)));
}
#define CP_COMMIT() asm volatile("cp.async.commit_group;" ::: "memory")
#define CP_WAIT0()  asm volatile("cp.async.wait_group 0;" ::: "memory")

// ---------------- y0 partials + split-bf16 x emit + ya/yb zeroing -----------
__global__ __launch_bounds__(256) void reduce_x_kernel(const float* __restrict__ x) {
    __shared__ float sred[256*4];
    const int b  = blockIdx.x >> 3;     // 32
    const int sg = blockIdx.x & 7;      // 8 groups x 128 s
    const int t  = threadIdx.x;
    const int q  = t & 63;              // d-quad: d = 4q
    const int rg = t >> 6;              // row-group 0..3
    const size_t rowbase = (size_t)b * S_ + sg * 128;

    {
        float4 z = make_float4(0.f, 0.f, 0.f, 0.f);
        ((float4*)g_ya)[blockIdx.x*256 + t] = z;
        ((float4*)g_yb)[blockIdx.x*256 + t] = z;
    }

    float4 a = make_float4(0.f, 0.f, 0.f, 0.f);
    #pragma unroll 4
    for (int it = 0; it < 32; it++) {
        const int s = it*4 + rg;
        const size_t o = (rowbase + s) * D_ + 4*q;
        const float4 v = *(const float4*)(x + o);
        __nv_bfloat162 h01 = __float22bfloat162_rn(make_float2(v.x, v.y));
        __nv_bfloat162 h23 = __float22bfloat162_rn(make_float2(v.z, v.w));
        __nv_bfloat162 l01 = __float22bfloat162_rn(make_float2(
            v.x - __bfloat162float(h01.x), v.y - __bfloat162float(h01.y)));
        __nv_bfloat162 l23 = __float22bfloat162_rn(make_float2(
            v.z - __bfloat162float(h23.x), v.w - __bfloat162float(h23.y)));
        __nv_bfloat162* dh = (__nv_bfloat162*)(g_xhi + o);
        __nv_bfloat162* dl = (__nv_bfloat162*)(g_xlo + o);
        dh[0] = h01; dh[1] = h23;
        dl[0] = l01; dl[1] = l23;
        a.x += v.x; a.y += v.y; a.z += v.z; a.w += v.w;
    }
    *(float4*)&sred[t*4] = a;
    __syncthreads();
    if (t < 64) {
        float4 r0 = *(const float4*)&sred[t*4];
        float4 r1 = *(const float4*)&sred[(t+64)*4];
        float4 r2 = *(const float4*)&sred[(t+128)*4];
        float4 r3 = *(const float4*)&sred[(t+192)*4];
        const float sc = 1.0f / (float)N_;
        float4 o = make_float4((r0.x+r1.x+r2.x+r3.x)*sc, (r0.y+r1.y+r2.y+r3.y)*sc,
                               (r0.z+r1.z+r2.z+r3.z)*sc, (r0.w+r1.w+r2.w+r3.w)*sc);
        *(float4*)&g_y0p[(sg*B_ + b)*D_ + 4*t] = o;
    }
}

// ---------------- capsule: s = y@W, v = squash(s), p = W@v (split-bf16) -----
// grid (N_, B_/CB) = (32, 8), 256 threads.
__global__ __launch_bounds__(256) void capsule_kernel(const float* __restrict__ W,
                                                      int ysel, float* __restrict__ vout_ext,
                                                      int compute_p) {
    extern __shared__ float sm[];
    float* sW = sm;                 // [D_][WPAD]
    float* sy = sW + D_*WPAD;       // [CB][D_]
    float* ss = sy + CB*D_;         // [CB][C_]
    float* sv = ss + CB*C_;         // [CB][C_]

    const int n  = blockIdx.x;
    const int b0 = blockIdx.y * CB;
    const int t  = threadIdx.x;

    // W[n] load: 4096 float4 via cp.async, 16 per thread
    {
        const uint32_t sWb = smem_u32(sW);
        const float4* Wn4 = (const float4*)(W + (size_t)n * D_ * C_);
        #pragma unroll
        for (int k = 0; k < 16; k++) {
            int j = t + k*256;               // float4 index: d = j>>4, q = j&15
            int d = j >> 4, q = j & 15;
            cp16(sWb + (uint32_t)(d*WPAD + 4*q)*4u, Wn4 + j);
        }
        CP_COMMIT();
    }
    // y rows for CB b's: CB*D_/256 = 4 per thread
    #pragma unroll
    for (int k = 0; k < CB*D_/256; k++) {
        int i = t + k*256;
        int bb = i >> 8, d = i & 255;
        if (ysel == 0) {
            float a = 0.f;
            #pragma unroll
            for (int p8 = 0; p8 < 8; p8++) a += g_y0p[(p8*B_ + b0+bb)*D_ + d];
            sy[bb*D_ + d] = a;
        } else {
            const float* ysrc = (ysel == 1) ? g_ya : g_yb;
            sy[bb*D_ + d] = ysrc[((size_t)(b0+bb)*N_ + n)*D_ + d];
        }
    }
    CP_WAIT0();
    __syncthreads();

    // s[b][c] = sum_d y[b][d] * W[d][c]; thread = (c = t&63, bb = t>>6)
    {
        const int c = t & 63, bb = t >> 6;
        const float* yr = sy + bb*D_;
        float s0 = 0.f, s1 = 0.f, s2 = 0.f, s3 = 0.f;
        #pragma unroll 8
        for (int d = 0; d < D_; d += 4) {
            s0 += yr[d+0] * sW[(d+0)*WPAD + c];
            s1 += yr[d+1] * sW[(d+1)*WPAD + c];
            s2 += yr[d+2] * sW[(d+2)*WPAD + c];
            s3 += yr[d+3] * sW[(d+3)*WPAD + c];
        }
        ss[bb*C_ + c] = (s0 + s1) + (s2 + s3);
    }
    __syncthreads();

    // squash: warps 0..CB-1, warp wid handles b = b0+wid
    const int wid = t >> 5, lane = t & 31;
    if (wid < CB) {
        float a0 = ss[wid*C_ + lane];
        float a1 = ss[wid*C_ + 32 + lane];
        float sq = a0*a0 + a1*a1;
        #pragma unroll
        for (int o = 16; o > 0; o >>= 1) sq += __shfl_xor_sync(0xffffffffu, sq, o);
        float sc = (sq / (1.f + sq)) * rsqrtf(sq + 1e-8f);
        float v0 = a0 * sc, v1 = a1 * sc;
        sv[wid*C_ + lane]      = v0;
        sv[wid*C_ + 32 + lane] = v1;
        float* vo = (vout_ext ? vout_ext : g_v) + ((size_t)(b0+wid)*N_ + n)*C_;
        vo[lane]      = v0;
        vo[32 + lane] = v1;
    }
    __syncthreads();

    // p[b][d] = sum_c W[d][c] * v[b][c]; thread = (bb = t>>6, dl = t&63)
    // float4 reads: sW row d has 17 float4; lanes dl -> bank-group 17*dl mod 8 distinct.
    if (compute_p) {
        const int bb = t >> 6, dl = t & 63;
        const float4* sv4 = (const float4*)(sv + bb*C_);
        #pragma unroll
        for (int dd = 0; dd < 4; dd++) {
            const int d = dd*64 + dl;
            const float4* wr4 = (const float4*)sW + d*(WPAD/4);  // WPAD/4 = 17
            float acc = 0.f;
            #pragma unroll
            for (int c4 = 0; c4 < 16; c4++) {
                float4 w = wr4[c4];
                float4 v = sv4[c4];
                acc += w.x*v.x + w.y*v.y + w.z*v.z + w.w*v.w;
            }
            size_t o = ((size_t)(b0+bb)*N_ + n)*D_ + d;
            __nv_bfloat16 h = __float2bfloat16(acc);
            g_phi[o] = h;
            g_plo[o] = __float2bfloat16(acc - __bfloat162float(h));
        }
    }
}

// ---------------- fused routing pass (tensor cores) --------------------------
// grid = B_*CHUNKS (1024), 256 threads, 3 CTAs/SM.
__global__ __launch_bounds__(TPB, 3) void pass_kernel(int first) {
    extern __shared__ char smc[];
    char* xh  = smc + O_XH;
    char* xl  = smc + O_XL;
    char* ph  = smc + O_PH;
    char* pl  = smc + O_PL;
    char* cth = smc + O_CTH;
    char* ctl = smc + O_CTL;
    float* cS = (float*)(smc + O_CS);   // aliases cth/ctl; live ranges disjoint

    const int t = threadIdx.x, wid = t >> 5, lane = t & 31;
    const int b  = blockIdx.x >> 5;
    const int ch = blockIdx.x & 31;
    const int s0 = ch * SCH;

    {
        const uint4* sh = (const uint4*)(g_xhi + ((size_t)(b*S_ + s0)) * D_);
        const uint4* sl = (const uint4*)(g_xlo + ((size_t)(b*S_ + s0)) * D_);
        #pragma unroll
        for (int i = t; i < SCH*32; i += TPB) {
            int s = i >> 5, q = i & 31;
            *(uint4*)(xh + s*XPB + q*16) = sh[i];
            *(uint4*)(xl + s*XPB + q*16) = sl[i];
        }
        const uint4* qh = (const uint4*)(g_phi + (size_t)b * N_ * D_);
        const uint4* ql = (const uint4*)(g_plo + (size_t)b * N_ * D_);
        #pragma unroll
        for (int i = t; i < N_*32; i += TPB) {
            int n = i >> 5, q = i & 31;
            *(uint4*)(ph + n*PPB + q*16) = qh[i];
            *(uint4*)(pl + n*PPB + q*16) = ql[i];
        }
    }
    __syncthreads();

    // phase 2: agree = X (32s x 256k) @ P^T -> warp tile m16(s) x n8(n), full K
    {
        const int pm = wid & 1, pn = wid >> 1;       // 2 x 4 warp grid
        const int s0w = pm * 16, n0w = pn * 8;
        const uint32_t aH = smem_u32(xh) + (s0w + (lane & 15))*XPB + (lane >> 4)*16;
        const uint32_t aL = smem_u32(xl) + (s0w + (lane & 15))*XPB + (lane >> 4)*16;
        const uint32_t bH = smem_u32(ph) + (n0w + (lane & 7))*PPB + ((lane >> 3) & 1)*16;
        const uint32_t bL = smem_u32(pl) + (n0w + (lane & 7))*PPB + ((lane >> 3) & 1)*16;
        float c1[4] = {0.f,0.f,0.f,0.f};
        float c2[4] = {0.f,0.f,0.f,0.f};
        float c3[4] = {0.f,0.f,0.f,0.f};
        #pragma unroll
        for (int k = 0; k < 16; k++) {
            uint32_t ah0,ah1,ah2,ah3, al0,al1,al2,al3, bh0,bh1, bl0,bl1;
            LDM_X4(ah0,ah1,ah2,ah3, aH + k*32);
            LDM_X4(al0,al1,al2,al3, aL + k*32);
            LDM_X2(bh0,bh1, bH + k*32);
            LDM_X2(bl0,bl1, bL + k*32);
            mma_bf16(c1, ah0,ah1,ah2,ah3, bh0,bh1);   // hi*hi
            mma_bf16(c2, ah0,ah1,ah2,ah3, bl0,bl1);   // hi*lo
            mma_bf16(c3, al0,al1,al2,al3, bh0,bh1);   // lo*hi
        }
        const int sr = s0w + (lane >> 2), nc = n0w + (lane & 3)*2;
        cS[sr*CPAD + nc]         = c1[0] + c2[0] + c3[0];
        cS[sr*CPAD + nc + 1]     = c1[1] + c2[1] + c3[1];
        cS[(sr+8)*CPAD + nc]     = c1[2] + c2[2] + c3[2];
        cS[(sr+8)*CPAD + nc + 1] = c1[3] + c2[3] + c3[3];
    }
    __syncthreads();

    // softmax over n per s-row, split read -> barrier -> compute+write (cS alias)
    {
        float lg[4];
        #pragma unroll
        for (int r = 0; r < 4; r++) {
            int s = wid*4 + r;
            lg[r] = cS[s*CPAD + lane];
            size_t li = ((size_t)b * S_ + s0 + s) * N_ + lane;
            if (first) g_logits[li] = lg[r];
            else       lg[r] += g_logits[li];
        }
        __syncthreads();
        #pragma unroll
        for (int r = 0; r < 4; r++) {
            int s = wid*4 + r;
            float v = lg[r];
            float mx = v;
            #pragma unroll
            for (int o = 16; o > 0; o >>= 1) mx = fmaxf(mx, __shfl_xor_sync(0xffffffffu, mx, o));
            float e = expf(v - mx);
            float sum = e;
            #pragma unroll
            for (int o = 16; o > 0; o >>= 1) sum += __shfl_xor_sync(0xffffffffu, sum, o);
            float cv = e / sum;
            __nv_bfloat16 hh = __float2bfloat16(cv);
            *(__nv_bfloat16*)(cth + lane*CTPB + s*2) = hh;
            *(__nv_bfloat16*)(ctl + lane*CTPB + s*2) =
                __float2bfloat16(cv - __bfloat162float(hh));
        }
    }
    __syncthreads();

    // phase 3: y = C^T (32n x 32k(s)) @ X (32s x 256d) -> warp m16(n) x 64d
    {
        const int wm = wid & 1, wd = wid >> 1;       // 2 x 4 warp grid
        const int n0w = wm * 16, d0w = wd * 64;
        const uint32_t aH = smem_u32(cth) + (n0w + (lane & 15))*CTPB + (lane >> 4)*16;
        const uint32_t aL = smem_u32(ctl) + (n0w + (lane & 15))*CTPB + (lane >> 4)*16;
        const int part  = lane >> 3;
        const int brow  = (part & 1)*8 + (lane & 7);
        const int bcolb = (part >> 1)*16;
        float acc[8][4];
        #pragma unroll
        for (int i = 0; i < 8; i++)
            #pragma unroll
            for (int j = 0; j < 4; j++) acc[i][j] = 0.f;

        #pragma unroll
        for (int ks = 0; ks < 2; ks++) {
            uint32_t ah0,ah1,ah2,ah3, al0,al1,al2,al3;
            LDM_X4(ah0,ah1,ah2,ah3, aH + ks*32);
            LDM_X4(al0,al1,al2,al3, aL + ks*32);
            #pragma unroll
            for (int j = 0; j < 4; j++) {
                const int dd = d0w + j*16;
                const uint32_t xb  = smem_u32(xh) + (ks*16 + brow)*XPB + dd*2 + bcolb;
                const uint32_t xlb = smem_u32(xl) + (ks*16 + brow)*XPB + dd*2 + bcolb;
                uint32_t bh0,bh1,bh2,bh3, bl0,bl1,bl2,bl3;
                LDM_X4T(bh0,bh1,bh2,bh3, xb);
                LDM_X4T(bl0,bl1,bl2,bl3, xlb);
                mma_bf16(acc[2*j],   ah0,ah1,ah2,ah3, bh0,bh1);
                mma_bf16(acc[2*j],   ah0,ah1,ah2,ah3, bl0,bl1);
                mma_bf16(acc[2*j],   al0,al1,al2,al3, bh0,bh1);
                mma_bf16(acc[2*j+1], ah0,ah1,ah2,ah3, bh2,bh3);
                mma_bf16(acc[2*j+1], ah0,ah1,ah2,ah3, bl2,bl3);
                mma_bf16(acc[2*j+1], al0,al1,al2,al3, bh2,bh3);
            }
        }
        float* yo = (first ? g_ya : g_yb) + (size_t)b * N_ * D_;
        const int nr = n0w + (lane >> 2);
        #pragma unroll
        for (int jj = 0; jj < 8; jj++) {
            int d = d0w + jj*8 + (lane & 3)*2;
            red_add_v2(&yo[nr*D_ + d],     acc[jj][0], acc[jj][1]);
            red_add_v2(&yo[(nr+8)*D_ + d], acc[jj][2], acc[jj][3]);
        }
    }
}

// ---------------- launch ----------------------------------------------------
extern "C" void kernel_launch(void* const* d_in, const int* in_sizes, int n_in,
                              void* d_out, int out_size) {
    (void)in_sizes; (void)n_in; (void)out_size;
    const float* x = (const float*)d_in[0];
    const float* W = (const float*)d_in[1];
    float* out = (float*)d_out;

    cudaFuncSetAttribute(capsule_kernel, cudaFuncAttributeMaxDynamicSharedMemorySize, CAPS_SMEM);
    cudaFuncSetAttribute(pass_kernel,    cudaFuncAttributeMaxDynamicSharedMemorySize, PASS_SMEM);

    reduce_x_kernel<<<B_*8, 256>>>(x);                 // y0 partials + bf16 x + zero ya/yb

    capsule_kernel<<<dim3(N_, B_/CB), 256, CAPS_SMEM>>>(W, 0, nullptr, 1); // v0, p0
    pass_kernel<<<B_*CHUNKS, TPB, PASS_SMEM>>>(1);                         // iter1 -> g_ya
    capsule_kernel<<<dim3(N_, B_/CB), 256, CAPS_SMEM>>>(W, 1, nullptr, 1); // v1, p1
    pass_kernel<<<B_*CHUNKS, TPB, PASS_SMEM>>>(0);                         // iter2 -> g_yb
    capsule_kernel<<<dim3(N_, B_/CB), 256, CAPS_SMEM>>>(W, 2, out, 0);     // v2 -> d_out
}

// round 13
// speedup vs baseline: 1.9480x; 1.0777x over previous
#include <cuda_runtime.h>
#include <cuda_bf16.h>
#include <math.h>
#include <stdint.h>

// Problem constants
#define B_  32
#define S_  1024
#define D_  256
#define N_  32
#define C_  64
#define M_  (B_*S_)

// pass kernel tiling (tensor-core version)
#define SCH 32                // s-values per block
#define CHUNKS (S_/SCH)       // 32
#define TPB 256               // 8 warps
#define XPB 528               // x smem row pitch BYTES (264 bf16; 33 x 16B, odd)
#define PPB 528               // p smem row pitch bytes
#define CTPB 80               // cT row pitch bytes (40 bf16; 5 x 16B, odd)
#define CPAD 36               // agree fp32 row stride (floats)

// smem byte offsets; cS (4608 B) aliases cth+ctl (5120 B) — live ranges disjoint
#define O_XH  0
#define O_XL  (O_XH + SCH*XPB)       // 16896
#define O_PH  (O_XL + SCH*XPB)       // 33792
#define O_PL  (O_PH + N_*PPB)        // 50688
#define O_CS  (O_PL + N_*PPB)        // 67584
#define O_CTH O_CS                   // 67584 (alias)
#define O_CTL (O_CTH + N_*CTPB)      // 70144
#define PASS_SMEM (O_CTL + N_*CTPB)  // 72704 B -> 3 CTAs/SM (218112 total)

// capsule: 4 b's per block, 256 threads, grid (N_, B_/4) = 256 blocks
#define WPAD 68               // W smem row stride (floats); 17 float4/row
#define CB 4                  // b's per capsule block
#define CAPS_SMEM ((D_*WPAD + CB*D_ + CB*C_ + CB*C_) * 4)  // 75776 B

// ---------------- scratch (device globals; no runtime allocation) ----------
__device__ float          g_y0p[8*B_*D_];     // per-chunk partials of (1/N) sum_s x
__device__ float          g_ya[B_*N_*D_];     // y for iter1
__device__ float          g_yb[B_*N_*D_];     // y for iter2
__device__ float          g_v [B_*N_*C_];
__device__ float          g_logits[B_*S_*N_];
__device__ __nv_bfloat16  g_phi[B_*N_*D_];
__device__ __nv_bfloat16  g_plo[B_*N_*D_];

// ---------------- PTX helpers ----------------------------------------------
__device__ __forceinline__ uint32_t smem_u32(const void* p) {
    uint32_t a;
    asm("{ .reg .u64 t; cvta.to.shared.u64 t, %1; cvt.u32.u64 %0, t; }" : "=r"(a) : "l"(p));
    return a;
}
#define LDM_X4(r0,r1,r2,r3,a) \
    asm volatile("ldmatrix.sync.aligned.m8n8.x4.shared.b16 {%0,%1,%2,%3}, [%4];" \
        : "=r"(r0),"=r"(r1),"=r"(r2),"=r"(r3) : "r"(a))
#define LDM_X2(r0,r1,a) \
    asm volatile("ldmatrix.sync.aligned.m8n8.x2.shared.b16 {%0,%1}, [%2];" \
        : "=r"(r0),"=r"(r1) : "r"(a))
#define LDM_X4T(r0,r1,r2,r3,a) \
    asm volatile("ldmatrix.sync.aligned.m8n8.x4.trans.shared.b16 {%0,%1,%2,%3}, [%4];" \
        : "=r"(r0),"=r"(r1),"=r"(r2),"=r"(r3) : "r"(a))
__device__ __forceinline__ void mma_bf16(float* c, uint32_t a0, uint32_t a1, uint32_t a2,
                                         uint32_t a3, uint32_t b0, uint32_t b1) {
    asm volatile(
        "mma.sync.aligned.m16n8k16.row.col.f32.bf16.bf16.f32 "
        "{%0,%1,%2,%3}, {%4,%5,%6,%7}, {%8,%9}, {%0,%1,%2,%3};"
        : "+f"(c[0]), "+f"(c[1]), "+f"(c[2]), "+f"(c[3])
        : "r"(a0), "r"(a1), "r"(a2), "r"(a3), "r"(b0), "r"(b1));
}
__device__ __forceinline__ void red_add_v2(float* p, float a, float b) {
    asm volatile("red.global.add.v2.f32 [%0], {%1, %2};"
        :: "l"(__cvta_generic_to_global(p)), "f"(a), "f"(b) : "memory");
}

// split a float4 into hi/lo bf16x2-pairs (uint2 each)
__device__ __forceinline__ void split4(float4 v, uint2& hh, uint2& ll) {
    __nv_bfloat162 h01 = __float22bfloat162_rn(make_float2(v.x, v.y));
    __nv_bfloat162 h23 = __float22bfloat162_rn(make_float2(v.z, v.w));
    __nv_bfloat162 l01 = __float22bfloat162_rn(make_float2(
        v.x - __bfloat162float(h01.x), v.y - __bfloat162float(h01.y)));
    __nv_bfloat162 l23 = __float22bfloat162_rn(make_float2(
        v.z - __bfloat162float(h23.x), v.w - __bfloat162float(h23.y)));
    hh = make_uint2(*(uint32_t*)&h01, *(uint32_t*)&h23);
    ll = make_uint2(*(uint32_t*)&l01, *(uint32_t*)&l23);
}

// ---------------- y0 partials + ya/yb zeroing (read-only reduction) ---------
__global__ __launch_bounds__(256) void reduce_x_kernel(const float* __restrict__ x) {
    __shared__ float sred[256*4];
    const int b  = blockIdx.x >> 3;     // 32
    const int sg = blockIdx.x & 7;      // 8 groups x 128 s
    const int t  = threadIdx.x;
    const int q  = t & 63;              // d-quad: d = 4q
    const int rg = t >> 6;              // row-group 0..3
    const size_t rowbase = (size_t)b * S_ + sg * 128;

    {
        float4 z = make_float4(0.f, 0.f, 0.f, 0.f);
        ((float4*)g_ya)[blockIdx.x*256 + t] = z;
        ((float4*)g_yb)[blockIdx.x*256 + t] = z;
    }

    float4 a = make_float4(0.f, 0.f, 0.f, 0.f);
    #pragma unroll 8
    for (int it = 0; it < 32; it++) {
        const int s = it*4 + rg;
        const float4 v = *(const float4*)(x + (rowbase + s) * D_ + 4*q);
        a.x += v.x; a.y += v.y; a.z += v.z; a.w += v.w;
    }
    *(float4*)&sred[t*4] = a;
    __syncthreads();
    if (t < 64) {
        float4 r0 = *(const float4*)&sred[t*4];
        float4 r1 = *(const float4*)&sred[(t+64)*4];
        float4 r2 = *(const float4*)&sred[(t+128)*4];
        float4 r3 = *(const float4*)&sred[(t+192)*4];
        const float sc = 1.0f / (float)N_;
        float4 o = make_float4((r0.x+r1.x+r2.x+r3.x)*sc, (r0.y+r1.y+r2.y+r3.y)*sc,
                               (r0.z+r1.z+r2.z+r3.z)*sc, (r0.w+r1.w+r2.w+r3.w)*sc);
        *(float4*)&g_y0p[(sg*B_ + b)*D_ + 4*t] = o;
    }
}

// ---------------- capsule: s = y@W, v = squash(s), p = W@v (split-bf16) -----
// grid (N_, B_/CB) = (32, 8), 256 threads.
__global__ __launch_bounds__(256) void capsule_kernel(const float* __restrict__ W,
                                                      int ysel, float* __restrict__ vout_ext,
                                                      int compute_p) {
    extern __shared__ float sm[];
    float* sW = sm;                 // [D_][WPAD]
    float* sy = sW + D_*WPAD;       // [CB][D_]
    float* ss = sy + CB*D_;         // [CB][C_]
    float* sv = ss + CB*C_;         // [CB][C_]

    const int n  = blockIdx.x;
    const int b0 = blockIdx.y * CB;
    const int t  = threadIdx.x;

    // W[n] load: 4096 float4 via plain LDG.128 -> STS.128 (NOT cp.async:
    // LDGSTS issue rate 8 cyc/op/SMSP makes 4096 copies ~8192 cyc; LDG+STS is ~8x cheaper)
    {
        const float4* Wn4 = (const float4*)(W + (size_t)n * D_ * C_);
        #pragma unroll
        for (int k = 0; k < 16; k += 4) {
            float4 w0 = Wn4[t + (k+0)*256];
            float4 w1 = Wn4[t + (k+1)*256];
            float4 w2 = Wn4[t + (k+2)*256];
            float4 w3 = Wn4[t + (k+3)*256];
            int j0 = t + (k+0)*256, j1 = t + (k+1)*256, j2 = t + (k+2)*256, j3 = t + (k+3)*256;
            *(float4*)&sW[(j0>>4)*WPAD + 4*(j0&15)] = w0;
            *(float4*)&sW[(j1>>4)*WPAD + 4*(j1&15)] = w1;
            *(float4*)&sW[(j2>>4)*WPAD + 4*(j2&15)] = w2;
            *(float4*)&sW[(j3>>4)*WPAD + 4*(j3&15)] = w3;
        }
    }
    // y rows for CB b's: CB*D_/256 = 4 per thread
    #pragma unroll
    for (int k = 0; k < CB*D_/256; k++) {
        int i = t + k*256;
        int bb = i >> 8, d = i & 255;
        if (ysel == 0) {
            float a = 0.f;
            #pragma unroll
            for (int p8 = 0; p8 < 8; p8++) a += g_y0p[(p8*B_ + b0+bb)*D_ + d];
            sy[bb*D_ + d] = a;
        } else {
            const float* ysrc = (ysel == 1) ? g_ya : g_yb;
            sy[bb*D_ + d] = ysrc[((size_t)(b0+bb)*N_ + n)*D_ + d];
        }
    }
    __syncthreads();

    // s[b][c] = sum_d y[b][d] * W[d][c]; thread = (c = t&63, bb = t>>6)
    {
        const int c = t & 63, bb = t >> 6;
        const float* yr = sy + bb*D_;
        float s0 = 0.f, s1 = 0.f, s2 = 0.f, s3 = 0.f;
        #pragma unroll 8
        for (int d = 0; d < D_; d += 4) {
            float4 yv = *(const float4*)(yr + d);
            s0 += yv.x * sW[(d+0)*WPAD + c];
            s1 += yv.y * sW[(d+1)*WPAD + c];
            s2 += yv.z * sW[(d+2)*WPAD + c];
            s3 += yv.w * sW[(d+3)*WPAD + c];
        }
        ss[bb*C_ + c] = (s0 + s1) + (s2 + s3);
    }
    __syncthreads();

    // squash: warps 0..CB-1, warp wid handles b = b0+wid
    const int wid = t >> 5, lane = t & 31;
    if (wid < CB) {
        float a0 = ss[wid*C_ + lane];
        float a1 = ss[wid*C_ + 32 + lane];
        float sq = a0*a0 + a1*a1;
        #pragma unroll
        for (int o = 16; o > 0; o >>= 1) sq += __shfl_xor_sync(0xffffffffu, sq, o);
        float sc = (sq / (1.f + sq)) * rsqrtf(sq + 1e-8f);
        float v0 = a0 * sc, v1 = a1 * sc;
        sv[wid*C_ + lane]      = v0;
        sv[wid*C_ + 32 + lane] = v1;
        float* vo = (vout_ext ? vout_ext : g_v) + ((size_t)(b0+wid)*N_ + n)*C_;
        vo[lane]      = v0;
        vo[32 + lane] = v1;
    }
    __syncthreads();

    // p[b][d] = sum_c W[d][c] * v[b][c]; thread = (bb = t>>6, dl = t&63)
    if (compute_p) {
        const int bb = t >> 6, dl = t & 63;
        const float4* sv4 = (const float4*)(sv + bb*C_);
        #pragma unroll
        for (int dd = 0; dd < 4; dd++) {
            const int d = dd*64 + dl;
            const float4* wr4 = (const float4*)sW + d*(WPAD/4);  // WPAD/4 = 17
            float acc = 0.f;
            #pragma unroll
            for (int c4 = 0; c4 < 16; c4++) {
                float4 w = wr4[c4];
                float4 v = sv4[c4];
                acc += w.x*v.x + w.y*v.y + w.z*v.z + w.w*v.w;
            }
            size_t o = ((size_t)(b0+bb)*N_ + n)*D_ + d;
            __nv_bfloat16 h = __float2bfloat16(acc);
            g_phi[o] = h;
            g_plo[o] = __float2bfloat16(acc - __bfloat162float(h));
        }
    }
}

// ---------------- fused routing pass (tensor cores) --------------------------
// grid = B_*CHUNKS (1024), 256 threads, 3 CTAs/SM. Reads fp32 x, splits on the fly.
__global__ __launch_bounds__(TPB, 3) void pass_kernel(const float* __restrict__ x, int first) {
    extern __shared__ char smc[];
    char* xh  = smc + O_XH;
    char* xl  = smc + O_XL;
    char* ph  = smc + O_PH;
    char* pl  = smc + O_PL;
    char* cth = smc + O_CTH;
    char* ctl = smc + O_CTL;
    float* cS = (float*)(smc + O_CS);   // aliases cth/ctl; live ranges disjoint

    const int t = threadIdx.x, wid = t >> 5, lane = t & 31;
    const int b  = blockIdx.x >> 5;
    const int ch = blockIdx.x & 31;
    const int s0 = ch * SCH;

    // load x tile fp32 and split-convert to bf16 hi/lo planes
    {
        const float4* xg = (const float4*)(x + ((size_t)(b*S_ + s0)) * D_);
        #pragma unroll
        for (int i = t; i < SCH*64; i += TPB) {   // 2048 float4
            int s = i >> 6, dq = i & 63;
            uint2 hh, ll;
            split4(xg[i], hh, ll);
            *(uint2*)(xh + s*XPB + dq*8) = hh;
            *(uint2*)(xl + s*XPB + dq*8) = ll;
        }
        const uint4* qh = (const uint4*)(g_phi + (size_t)b * N_ * D_);
        const uint4* ql = (const uint4*)(g_plo + (size_t)b * N_ * D_);
        #pragma unroll
        for (int i = t; i < N_*32; i += TPB) {
            int n = i >> 5, q = i & 31;
            *(uint4*)(ph + n*PPB + q*16) = qh[i];
            *(uint4*)(pl + n*PPB + q*16) = ql[i];
        }
    }
    __syncthreads();

    // phase 2: agree = X (32s x 256k) @ P^T -> warp tile m16(s) x n8(n), full K
    {
        const int pm = wid & 1, pn = wid >> 1;       // 2 x 4 warp grid
        const int s0w = pm * 16, n0w = pn * 8;
        const uint32_t aH = smem_u32(xh) + (s0w + (lane & 15))*XPB + (lane >> 4)*16;
        const uint32_t aL = smem_u32(xl) + (s0w + (lane & 15))*XPB + (lane >> 4)*16;
        const uint32_t bH = smem_u32(ph) + (n0w + (lane & 7))*PPB + ((lane >> 3) & 1)*16;
        const uint32_t bL = smem_u32(pl) + (n0w + (lane & 7))*PPB + ((lane >> 3) & 1)*16;
        float c1[4] = {0.f,0.f,0.f,0.f};
        float c2[4] = {0.f,0.f,0.f,0.f};
        float c3[4] = {0.f,0.f,0.f,0.f};
        #pragma unroll
        for (int k = 0; k < 16; k++) {
            uint32_t ah0,ah1,ah2,ah3, al0,al1,al2,al3, bh0,bh1, bl0,bl1;
            LDM_X4(ah0,ah1,ah2,ah3, aH + k*32);
            LDM_X4(al0,al1,al2,al3, aL + k*32);
            LDM_X2(bh0,bh1, bH + k*32);
            LDM_X2(bl0,bl1, bL + k*32);
            mma_bf16(c1, ah0,ah1,ah2,ah3, bh0,bh1);   // hi*hi
            mma_bf16(c2, ah0,ah1,ah2,ah3, bl0,bl1);   // hi*lo
            mma_bf16(c3, al0,al1,al2,al3, bh0,bh1);   // lo*hi
        }
        const int sr = s0w + (lane >> 2), nc = n0w + (lane & 3)*2;
        cS[sr*CPAD + nc]         = c1[0] + c2[0] + c3[0];
        cS[sr*CPAD + nc + 1]     = c1[1] + c2[1] + c3[1];
        cS[(sr+8)*CPAD + nc]     = c1[2] + c2[2] + c3[2];
        cS[(sr+8)*CPAD + nc + 1] = c1[3] + c2[3] + c3[3];
    }
    __syncthreads();

    // softmax over n per s-row, split read -> barrier -> compute+write (cS alias)
    {
        float lg[4];
        #pragma unroll
        for (int r = 0; r < 4; r++) {
            int s = wid*4 + r;
            lg[r] = cS[s*CPAD + lane];
            size_t li = ((size_t)b * S_ + s0 + s) * N_ + lane;
            if (first) g_logits[li] = lg[r];
            else       lg[r] += g_logits[li];
        }
        __syncthreads();
        #pragma unroll
        for (int r = 0; r < 4; r++) {
            int s = wid*4 + r;
            float v = lg[r];
            float mx = v;
            #pragma unroll
            for (int o = 16; o > 0; o >>= 1) mx = fmaxf(mx, __shfl_xor_sync(0xffffffffu, mx, o));
            float e = expf(v - mx);
            float sum = e;
            #pragma unroll
            for (int o = 16; o > 0; o >>= 1) sum += __shfl_xor_sync(0xffffffffu, sum, o);
            float cv = e / sum;
            __nv_bfloat16 hh = __float2bfloat16(cv);
            *(__nv_bfloat16*)(cth + lane*CTPB + s*2) = hh;
            *(__nv_bfloat16*)(ctl + lane*CTPB + s*2) =
                __float2bfloat16(cv - __bfloat162float(hh));
        }
    }
    __syncthreads();

    // phase 3: y = C^T (32n x 32k(s)) @ X (32s x 256d) -> warp m16(n) x 64d
    {
        const int wm = wid & 1, wd = wid >> 1;       // 2 x 4 warp grid
        const int n0w = wm * 16, d0w = wd * 64;
        const uint32_t aH = smem_u32(cth) + (n0w + (lane & 15))*CTPB + (lane >> 4)*16;
        const uint32_t aL = smem_u32(ctl) + (n0w + (lane & 15))*CTPB + (lane >> 4)*16;
        const int part  = lane >> 3;
        const int brow  = (part & 1)*8 + (lane & 7);
        const int bcolb = (part >> 1)*16;
        float acc[8][4];
        #pragma unroll
        for (int i = 0; i < 8; i++)
            #pragma unroll
            for (int j = 0; j < 4; j++) acc[i][j] = 0.f;

        #pragma unroll
        for (int ks = 0; ks < 2; ks++) {
            uint32_t ah0,ah1,ah2,ah3, al0,al1,al2,al3;
            LDM_X4(ah0,ah1,ah2,ah3, aH + ks*32);
            LDM_X4(al0,al1,al2,al3, aL + ks*32);
            #pragma unroll
            for (int j = 0; j < 4; j++) {
                const int dd = d0w + j*16;
                const uint32_t xb  = smem_u32(xh) + (ks*16 + brow)*XPB + dd*2 + bcolb;
                const uint32_t xlb = smem_u32(xl) + (ks*16 + brow)*XPB + dd*2 + bcolb;
                uint32_t bh0,bh1,bh2,bh3, bl0,bl1,bl2,bl3;
                LDM_X4T(bh0,bh1,bh2,bh3, xb);
                LDM_X4T(bl0,bl1,bl2,bl3, xlb);
                mma_bf16(acc[2*j],   ah0,ah1,ah2,ah3, bh0,bh1);
                mma_bf16(acc[2*j],   ah0,ah1,ah2,ah3, bl0,bl1);
                mma_bf16(acc[2*j],   al0,al1,al2,al3, bh0,bh1);
                mma_bf16(acc[2*j+1], ah0,ah1,ah2,ah3, bh2,bh3);
                mma_bf16(acc[2*j+1], ah0,ah1,ah2,ah3, bl2,bl3);
                mma_bf16(acc[2*j+1], al0,al1,al2,al3, bh2,bh3);
            }
        }
        float* yo = (first ? g_ya : g_yb) + (size_t)b * N_ * D_;
        const int nr = n0w + (lane >> 2);
        #pragma unroll
        for (int jj = 0; jj < 8; jj++) {
            int d = d0w + jj*8 + (lane & 3)*2;
            red_add_v2(&yo[nr*D_ + d],     acc[jj][0], acc[jj][1]);
            red_add_v2(&yo[(nr+8)*D_ + d], acc[jj][2], acc[jj][3]);
        }
    }
}

// ---------------- launch ----------------------------------------------------
extern "C" void kernel_launch(void* const* d_in, const int* in_sizes, int n_in,
                              void* d_out, int out_size) {
    (void)in_sizes; (void)n_in; (void)out_size;
    const float* x = (const float*)d_in[0];
    const float* W = (const float*)d_in[1];
    float* out = (float*)d_out;

    cudaFuncSetAttribute(capsule_kernel, cudaFuncAttributeMaxDynamicSharedMemorySize, CAPS_SMEM);
    cudaFuncSetAttribute(pass_kernel,    cudaFuncAttributeMaxDynamicSharedMemorySize, PASS_SMEM);

    reduce_x_kernel<<<B_*8, 256>>>(x);                 // y0 partials + zero ya/yb

    capsule_kernel<<<dim3(N_, B_/CB), 256, CAPS_SMEM>>>(W, 0, nullptr, 1); // v0, p0
    pass_kernel<<<B_*CHUNKS, TPB, PASS_SMEM>>>(x, 1);                      // iter1 -> g_ya
    capsule_kernel<<<dim3(N_, B_/CB), 256, CAPS_SMEM>>>(W, 1, nullptr, 1); // v1, p1
    pass_kernel<<<B_*CHUNKS, TPB, PASS_SMEM>>>(x, 0);                      // iter2 -> g_yb
    capsule_kernel<<<dim3(N_, B_/CB), 256, CAPS_SMEM>>>(W, 2, out, 0);     // v2 -> d_out
}